// round 1
// baseline (speedup 1.0000x reference)
#include <cuda_runtime.h>

// Monarch / block-diagonal butterfly linear
//   x:  (16384, 4096) f32
//   w1: (4, 192, 1024) f32   stage1: out1[b,k,q] = sum_p x[b,k*1024+p] * w1[k,q,p]
//   w2: (4, 1024, 192) f32   stage2: out[b,l*1024+s] = sum_r mid[b,l,r] * w2[l,s,r] + bias
//   block transpose: q = l*48 + b1  ->  r = k*48 + b1  (done by epilogue scatter of stage1)

constexpr int BATCH = 16384;
constexpr int IN_F  = 4096;
constexpr int OUT_F = 4096;
constexpr int NB1 = 4, NB2 = 4, B1C = 48;
constexpr int P = IN_F / NB1;   // 1024  (stage1 K)
constexpr int Q = NB2 * B1C;    // 192   (stage1 N per block)
constexpr int R = NB1 * B1C;    // 192   (stage2 K)
constexpr int S = OUT_F / NB2;  // 1024  (stage2 N per block)
constexpr int MIDW = NB2 * R;   // 768

// Scratch for the block-transposed intermediate (48 MB). Device-global array:
// the only allocation mechanism allowed under the harness rules.
__device__ float g_mid[(size_t)BATCH * MIDW];

constexpr int BM = 128, BN = 64, BK = 16;
constexpr int TM = 8,  TN = 4;           // 256 threads * (8x4) = 128x64 tile

// ---------------------------------------------------------------------------
// Stage 1: for each k-block, C(16384 x 192) = X_k(16384 x 1024) * W1_k^T
// Epilogue scatters into block-transposed layout in g_mid.
// ---------------------------------------------------------------------------
__global__ __launch_bounds__(256) void stage1_kernel(
    const float* __restrict__ x, const float* __restrict__ w1)
{
    __shared__ float As[BK][BM + 4];
    __shared__ float Bs[BK][BN + 4];

    const int kblk = blockIdx.z;          // 0..3
    const int n0   = blockIdx.y * BN;     // 0,64,128
    const int m0   = blockIdx.x * BM;
    const int t  = threadIdx.x;
    const int ty = t >> 4;                // 0..15 -> rows
    const int tx = t & 15;                // 0..15 -> cols

    const float* Ag = x  + (size_t)m0 * IN_F + (size_t)kblk * P;
    const float* Bg = w1 + (size_t)kblk * Q * P + (size_t)n0 * P;

    float c[TM][TN];
#pragma unroll
    for (int i = 0; i < TM; i++)
#pragma unroll
        for (int j = 0; j < TN; j++) c[i][j] = 0.f;

    for (int k0 = 0; k0 < P; k0 += BK) {
        // A tile: 128x16 = 512 float4, 2 per thread
#pragma unroll
        for (int r = 0; r < 2; r++) {
            int u  = t + r * 256;
            int m  = u >> 2;
            int kq = (u & 3) << 2;
            float4 v = *reinterpret_cast<const float4*>(Ag + (size_t)m * IN_F + k0 + kq);
            As[kq + 0][m] = v.x; As[kq + 1][m] = v.y;
            As[kq + 2][m] = v.z; As[kq + 3][m] = v.w;
        }
        // B tile: 64x16 = 256 float4, 1 per thread
        {
            int q  = t >> 2;
            int kq = (t & 3) << 2;
            float4 v = *reinterpret_cast<const float4*>(Bg + (size_t)q * P + k0 + kq);
            Bs[kq + 0][q] = v.x; Bs[kq + 1][q] = v.y;
            Bs[kq + 2][q] = v.z; Bs[kq + 3][q] = v.w;
        }
        __syncthreads();

#pragma unroll
        for (int kk = 0; kk < BK; kk++) {
            float a[TM], b[TN];
#pragma unroll
            for (int i = 0; i < TM; i++) a[i] = As[kk][ty * TM + i];
#pragma unroll
            for (int j = 0; j < TN; j++) b[j] = Bs[kk][tx * TN + j];
#pragma unroll
            for (int i = 0; i < TM; i++)
#pragma unroll
                for (int j = 0; j < TN; j++)
                    c[i][j] = fmaf(a[i], b[j], c[i][j]);
        }
        __syncthreads();
    }

    // Epilogue: q = l*48 + b1  ->  mid[m][l*192 + kblk*48 + b1]
#pragma unroll
    for (int i = 0; i < TM; i++) {
        int m = m0 + ty * TM + i;
#pragma unroll
        for (int j = 0; j < TN; j++) {
            int q  = n0 + tx * TN + j;
            int l  = q / B1C;
            int b1 = q - l * B1C;
            g_mid[(size_t)m * MIDW + l * R + kblk * B1C + b1] = c[i][j];
        }
    }
}

// ---------------------------------------------------------------------------
// Stage 2: for each l-block, C(16384 x 1024) = MID_l(16384 x 192) * W2_l^T + bias
// ---------------------------------------------------------------------------
__global__ __launch_bounds__(256) void stage2_kernel(
    const float* __restrict__ w2, const float* __restrict__ bias,
    float* __restrict__ out)
{
    __shared__ float As[BK][BM + 4];
    __shared__ float Bs[BK][BN + 4];

    const int lblk = blockIdx.z;          // 0..3
    const int n0   = blockIdx.y * BN;     // 0..960
    const int m0   = blockIdx.x * BM;
    const int t  = threadIdx.x;
    const int ty = t >> 4;
    const int tx = t & 15;

    const float* Ag = g_mid + (size_t)m0 * MIDW + (size_t)lblk * R;
    const float* Bg = w2    + (size_t)lblk * S * R + (size_t)n0 * R;

    float c[TM][TN];
#pragma unroll
    for (int i = 0; i < TM; i++)
#pragma unroll
        for (int j = 0; j < TN; j++) c[i][j] = 0.f;

    for (int k0 = 0; k0 < R; k0 += BK) {   // 12 iterations
#pragma unroll
        for (int r = 0; r < 2; r++) {
            int u  = t + r * 256;
            int m  = u >> 2;
            int kq = (u & 3) << 2;
            float4 v = *reinterpret_cast<const float4*>(Ag + (size_t)m * MIDW + k0 + kq);
            As[kq + 0][m] = v.x; As[kq + 1][m] = v.y;
            As[kq + 2][m] = v.z; As[kq + 3][m] = v.w;
        }
        {
            int q  = t >> 2;
            int kq = (t & 3) << 2;
            float4 v = *reinterpret_cast<const float4*>(Bg + (size_t)q * R + k0 + kq);
            Bs[kq + 0][q] = v.x; Bs[kq + 1][q] = v.y;
            Bs[kq + 2][q] = v.z; Bs[kq + 3][q] = v.w;
        }
        __syncthreads();

#pragma unroll
        for (int kk = 0; kk < BK; kk++) {
            float a[TM], b[TN];
#pragma unroll
            for (int i = 0; i < TM; i++) a[i] = As[kk][ty * TM + i];
#pragma unroll
            for (int j = 0; j < TN; j++) b[j] = Bs[kk][tx * TN + j];
#pragma unroll
            for (int i = 0; i < TM; i++)
#pragma unroll
                for (int j = 0; j < TN; j++)
                    c[i][j] = fmaf(a[i], b[j], c[i][j]);
        }
        __syncthreads();
    }

    // Epilogue: add bias, store
#pragma unroll
    for (int j = 0; j < TN; j++) {
        int sg = n0 + tx * TN + j;
        float bv = bias[lblk * S + sg];
#pragma unroll
        for (int i = 0; i < TM; i++) {
            int m = m0 + ty * TM + i;
            out[(size_t)m * OUT_F + lblk * S + sg] = c[i][j] + bv;
        }
    }
}

extern "C" void kernel_launch(void* const* d_in, const int* in_sizes, int n_in,
                              void* d_out, int out_size)
{
    const float* x    = (const float*)d_in[0];
    const float* w1   = (const float*)d_in[1];
    const float* w2   = (const float*)d_in[2];
    const float* bias = (const float*)d_in[3];
    float* out = (float*)d_out;

    dim3 g1(BATCH / BM, Q / BN, NB1);   // (128, 3, 4)
    stage1_kernel<<<g1, 256>>>(x, w1);

    dim3 g2(BATCH / BM, S / BN, NB2);   // (128, 16, 4)
    stage2_kernel<<<g2, 256>>>(w2, bias, out);
}

// round 5
// speedup vs baseline: 1.5787x; 1.5787x over previous
#include <cuda_runtime.h>
#include <cuda_bf16.h>
#include <cstdint>

// Monarch butterfly linear.
// tcgen05 bf16 split-precision path compiled ONLY in arch-specific (sm_103a)
// device passes; plain compute_103 passes get a correct fp32 SIMT fallback.
//   stage1: per k-block  C(16384x192) = X_k(16384x1024) @ W1_k^T -> g_mid
//   stage2: per l-block  OUT(16384x1024) = MID_l(16384x192) @ W2_l^T + bias

#if defined(__CUDA_ARCH__) && (defined(__CUDA_ARCH_FEAT_SM103_ALL) || defined(__CUDA_ARCH_FEAT_SM100_ALL))
#define HAS_TCGEN05 1
#else
#define HAS_TCGEN05 0
#endif

constexpr int BATCH = 16384;
constexpr int IN_F  = 4096;
constexpr int OUT_F = 4096;
constexpr int NB1 = 4, NB2 = 4, B1C = 48;
constexpr int P = 1024;   // stage1 K
constexpr int Q = 192;    // stage1 N
constexpr int R = 192;    // stage2 K
constexpr int S = 1024;   // stage2 N per l-block
constexpr int MIDW = NB2 * R;  // 768

constexpr int BM = 128;
constexpr int BK = 64;    // 64 bf16 = 128B = one SW128 atom row
constexpr int N2T = 128;  // stage2 N tile (shared by both paths)

// Intermediate scratch, 48 MB. tcgen05 path: packed (bf16 hi | bf16 lo).
// Fallback path: raw fp32 bits. Paths never mix at runtime (one fatbin
// variant executes all kernels).
__device__ uint32_t g_mid[(size_t)BATCH * MIDW];

// Shared-memory budgets (host-visible, path-independent).
constexpr int HDR = 1024;
// tcgen05 stage1 buffer: Ahi 16K | Alo 16K | Bhi 24K | Blo 24K = 80K
constexpr int S1_A_LO = 16384, S1_B_HI = 32768, S1_B_LO = 57344, S1_BUF = 81920;
constexpr int SMEM1 = 1024 + HDR + 2 * S1_BUF;          // 165888
// tcgen05 stage2 buffer (N2T=128): Ahi 16K | Alo 16K | Bhi 16K | Blo 16K = 64K
constexpr int S2_A_LO = 16384, S2_B_HI = 32768, S2_B_LO = 49152, S2_BUF = 65536;
constexpr int SMEM2 = 1024 + HDR + 2 * S2_BUF;          // 133120

#if HAS_TCGEN05
// ---------------------------------------------------------------------------
// PTX helpers (arch-specific pass only)
// ---------------------------------------------------------------------------
__device__ __forceinline__ uint32_t smem_u32(const void* p) {
    uint32_t a;
    asm("{ .reg .u64 t; cvta.to.shared.u64 t, %1; cvt.u32.u64 %0, t; }" : "=r"(a) : "l"(p));
    return a;
}
__device__ __forceinline__ bool elect_one() {
    uint32_t pred;
    asm volatile("{ .reg .pred p; elect.sync _|p, 0xFFFFFFFF; selp.b32 %0, 1, 0, p; }" : "=r"(pred));
    return pred != 0;
}
__device__ __forceinline__ uint32_t sw128(uint32_t byte_off) {
    return byte_off ^ ((byte_off >> 3) & 0x70);
}
static constexpr uint64_t DESC_BASE_SW128 =
    (uint64_t(2)  << 61) | (uint64_t(1) << 46) | (uint64_t(64) << 32) | (uint64_t(1) << 16);
__device__ __forceinline__ uint64_t make_desc(uint32_t smem_addr) {
    return DESC_BASE_SW128 | ((uint64_t)(smem_addr >> 4) & 0x3FFF);
}

#define TC_ALLOC(smem_ptr_addr, n) \
    asm volatile("tcgen05.alloc.cta_group::1.sync.aligned.shared::cta.b32 [%0], %1;" \
                 :: "r"(smem_ptr_addr), "r"((uint32_t)(n)) : "memory")
#define TC_DEALLOC(tmem, n) \
    asm volatile("tcgen05.dealloc.cta_group::1.sync.aligned.b32 %0, %1;" :: "r"(tmem), "r"((uint32_t)(n)))
#define TC_RELINQ() \
    asm volatile("tcgen05.relinquish_alloc_permit.cta_group::1.sync.aligned;")
#define TC_COMMIT(mbar) \
    asm volatile("tcgen05.commit.cta_group::1.mbarrier::arrive::one.shared::cluster.b64 [%0];" \
                 :: "r"(mbar) : "memory")
#define TC_FENCE_AFTER()  asm volatile("tcgen05.fence::after_thread_sync;" ::: "memory")
#define TC_WAIT_LD()      asm volatile("tcgen05.wait::ld.sync.aligned;" ::: "memory")
#define FENCE_ASYNC()     asm volatile("fence.proxy.async.shared::cta;" ::: "memory")
#define MBAR_INIT(mbar, n) \
    asm volatile("mbarrier.init.shared.b64 [%0], %1;" :: "r"(mbar), "r"((uint32_t)(n)) : "memory")

__device__ __forceinline__ void mbar_wait(uint32_t mbar, int parity) {
    uint32_t done;
    asm volatile("{ .reg .pred p; mbarrier.try_wait.parity.acquire.cta.shared::cta.b64 p, [%1], %2; selp.b32 %0, 1, 0, p; }"
                 : "=r"(done) : "r"(mbar), "r"((uint32_t)parity) : "memory");
    if (!done) {
        asm volatile(
            "{ .reg .pred P1;\n"
            "WAIT_%=: mbarrier.try_wait.parity.acquire.cta.shared::cta.b64 P1, [%0], %1, 0x989680;\n"
            "@P1 bra.uni DONE_%=;\n"
            "bra.uni WAIT_%=;\n"
            "DONE_%=: }"
            :: "r"(mbar), "r"((uint32_t)parity) : "memory");
    }
}

__device__ __forceinline__ void mma_f16_ss(uint32_t d_tmem, uint64_t a_desc, uint64_t b_desc,
                                           uint32_t idesc, bool acc) {
    uint32_t en = acc ? 1u : 0u;
    asm volatile(
        "{ .reg .pred p; setp.ne.u32 p, %4, 0;\n"
        "tcgen05.mma.cta_group::1.kind::f16 [%0], %1, %2, %3, {%5, %5, %5, %5}, p; }"
        :: "r"(d_tmem), "l"(a_desc), "l"(b_desc), "r"(idesc), "r"(en), "r"(0u)
        : "memory");
}

#define TC_LD_X32(r, addr) \
    asm volatile("tcgen05.ld.sync.aligned.32x32b.x32.b32 " \
        "{%0,%1,%2,%3,%4,%5,%6,%7,%8,%9,%10,%11,%12,%13,%14,%15," \
        "%16,%17,%18,%19,%20,%21,%22,%23,%24,%25,%26,%27,%28,%29,%30,%31}, [%32];" \
        : "=r"((r)[0]),"=r"((r)[1]),"=r"((r)[2]),"=r"((r)[3]),"=r"((r)[4]),"=r"((r)[5]),"=r"((r)[6]),"=r"((r)[7]), \
          "=r"((r)[8]),"=r"((r)[9]),"=r"((r)[10]),"=r"((r)[11]),"=r"((r)[12]),"=r"((r)[13]),"=r"((r)[14]),"=r"((r)[15]), \
          "=r"((r)[16]),"=r"((r)[17]),"=r"((r)[18]),"=r"((r)[19]),"=r"((r)[20]),"=r"((r)[21]),"=r"((r)[22]),"=r"((r)[23]), \
          "=r"((r)[24]),"=r"((r)[25]),"=r"((r)[26]),"=r"((r)[27]),"=r"((r)[28]),"=r"((r)[29]),"=r"((r)[30]),"=r"((r)[31]) \
        : "r"(addr))

// idesc: dtype=F32 (1<<4), atype=BF16 (1<<7), btype=BF16 (1<<10), N/8 <<17, M/16 <<24
constexpr uint32_t IDESC1 = (8u << 24) | ((Q   / 8u) << 17) | (1u << 10) | (1u << 7) | (1u << 4); // M=128,N=192
constexpr uint32_t IDESC2 = (8u << 24) | ((N2T / 8u) << 17) | (1u << 10) | (1u << 7) | (1u << 4); // M=128,N=128
#endif  // HAS_TCGEN05

// ---------------------------------------------------------------------------
// Stage 1: grid (128, 4), 256 threads, dyn smem SMEM1
// ---------------------------------------------------------------------------
__global__ __launch_bounds__(256) void stage1_kernel(const float* __restrict__ x,
                                                     const float* __restrict__ w1)
{
#if HAS_TCGEN05
    extern __shared__ char smem_raw[];
    const uint32_t raw = smem_u32(smem_raw);
    const uint32_t base = (raw + 1023u) & ~1023u;
    char* sm = smem_raw + (base - raw);

    const int t = threadIdx.x;
    const int wid = t >> 5, lid = t & 31;
    const int m0 = blockIdx.x * BM;
    const int kblk = blockIdx.y;

    if (wid == 0) TC_ALLOC(base, 512);
    if (t == 0) { MBAR_INIT(base + 8, 1); MBAR_INIT(base + 16, 1); }
    __syncthreads();
    uint32_t tmem;
    asm volatile("ld.shared.b32 %0, [%1];" : "=r"(tmem) : "r"(base));

    const float* Ag = x  + (size_t)m0 * IN_F + (size_t)kblk * P;
    const float* Bg = w1 + (size_t)kblk * Q * P;

    int phase[2] = {0, 0};

    for (int c = 0; c < P / BK; ++c) {            // 16 chunks
        const int b = c & 1;
        if (c >= 2) { mbar_wait(base + 8 + b * 8, phase[b]); phase[b] ^= 1; }
        const int k0 = c * BK;
        char* Ahi = sm + HDR + b * S1_BUF;
        char* Alo = sm + HDR + b * S1_BUF + S1_A_LO;
        char* Bhi = sm + HDR + b * S1_BUF + S1_B_HI;
        char* Blo = sm + HDR + b * S1_BUF + S1_B_LO;

        for (int u = t; u < 128 * 32; u += 256) {
            int row = u >> 5, cp = u & 31;
            float2 v = *reinterpret_cast<const float2*>(Ag + (size_t)row * IN_F + k0 + 2 * cp);
            __nv_bfloat162 h = __floats2bfloat162_rn(v.x, v.y);
            __nv_bfloat162 l = __floats2bfloat162_rn(v.x - __bfloat162float(h.x),
                                                     v.y - __bfloat162float(h.y));
            uint32_t off = sw128(row * 128 + cp * 4);
            *reinterpret_cast<uint32_t*>(Ahi + off) = *reinterpret_cast<uint32_t*>(&h);
            *reinterpret_cast<uint32_t*>(Alo + off) = *reinterpret_cast<uint32_t*>(&l);
        }
        for (int u = t; u < 192 * 32; u += 256) {
            int row = u >> 5, cp = u & 31;
            float2 v = *reinterpret_cast<const float2*>(Bg + (size_t)row * P + k0 + 2 * cp);
            __nv_bfloat162 h = __floats2bfloat162_rn(v.x, v.y);
            __nv_bfloat162 l = __floats2bfloat162_rn(v.x - __bfloat162float(h.x),
                                                     v.y - __bfloat162float(h.y));
            uint32_t off = sw128(row * 128 + cp * 4);
            *reinterpret_cast<uint32_t*>(Bhi + off) = *reinterpret_cast<uint32_t*>(&h);
            *reinterpret_cast<uint32_t*>(Blo + off) = *reinterpret_cast<uint32_t*>(&l);
        }
        FENCE_ASYNC();
        __syncthreads();

        if (wid == 0 && elect_one()) {
            uint64_t dAh = make_desc(base + HDR + b * S1_BUF);
            uint64_t dAl = make_desc(base + HDR + b * S1_BUF + S1_A_LO);
            uint64_t dBh = make_desc(base + HDR + b * S1_BUF + S1_B_HI);
            uint64_t dBl = make_desc(base + HDR + b * S1_BUF + S1_B_LO);
            bool first = (c == 0);
#pragma unroll
            for (int ks = 0; ks < 4; ks++)
                mma_f16_ss(tmem, dAh + ks * 2, dBh + ks * 2, IDESC1, !(first && ks == 0));
#pragma unroll
            for (int ks = 0; ks < 4; ks++)
                mma_f16_ss(tmem, dAh + ks * 2, dBl + ks * 2, IDESC1, true);
#pragma unroll
            for (int ks = 0; ks < 4; ks++)
                mma_f16_ss(tmem, dAl + ks * 2, dBh + ks * 2, IDESC1, true);
            TC_COMMIT(base + 8 + b * 8);
        }
    }

    mbar_wait(base + 8, phase[0]);
    mbar_wait(base + 16, phase[1]);
    TC_FENCE_AFTER();
    __syncthreads();

    float* stg = reinterpret_cast<float*>(sm + HDR);       // 128 x 193 f32
    if (wid < 4) {
        const int row = wid * 32 + lid;
#pragma unroll
        for (int cc = 0; cc < 6; ++cc) {
            uint32_t r32[32];
            TC_LD_X32(r32, tmem + cc * 32);
            TC_WAIT_LD();
#pragma unroll
            for (int j = 0; j < 32; ++j) stg[row * 193 + cc * 32 + j] = __uint_as_float(r32[j]);
        }
    }
    __syncthreads();

    for (int u = t; u < 128 * 192; u += 256) {
        int r = u / 192, q = u - r * 192;
        int l = q / B1C, b1 = q - l * B1C;
        float f = stg[r * 193 + q];
        __nv_bfloat16 h = __float2bfloat16_rn(f);
        __nv_bfloat16 lo = __float2bfloat16_rn(f - __bfloat162float(h));
        uint32_t packed = (uint32_t)__bfloat16_as_ushort(h) |
                          ((uint32_t)__bfloat16_as_ushort(lo) << 16);
        g_mid[(size_t)(m0 + r) * MIDW + l * R + kblk * B1C + b1] = packed;
    }

    __syncthreads();
    if (wid == 0) { TC_RELINQ(); TC_DEALLOC(tmem, 512); }
#else
    // ---- fp32 SIMT fallback: CTA computes 128 x 192, K=1024 ----
    extern __shared__ char smem_raw[];
    float* As = reinterpret_cast<float*>(smem_raw);          // [16][132]
    float* Bs = As + 16 * 132;                               // [16][196]

    const int t = threadIdx.x;
    const int ty = t >> 4;           // 0..15 -> row groups of 8
    const int tx = t & 15;           // 0..15 -> col groups of 12
    const int m0 = blockIdx.x * BM;
    const int kblk = blockIdx.y;

    const float* Ag = x  + (size_t)m0 * IN_F + (size_t)kblk * P;
    const float* Bg = w1 + (size_t)kblk * Q * P;

    float c[8][12];
#pragma unroll
    for (int i = 0; i < 8; i++)
#pragma unroll
        for (int j = 0; j < 12; j++) c[i][j] = 0.f;

    for (int k0 = 0; k0 < P; k0 += 16) {
#pragma unroll
        for (int rr = 0; rr < 2; rr++) {
            int u = t + rr * 256;
            int m = u >> 2, kq = (u & 3) << 2;
            float4 v = *reinterpret_cast<const float4*>(Ag + (size_t)m * IN_F + k0 + kq);
            As[(kq + 0) * 132 + m] = v.x; As[(kq + 1) * 132 + m] = v.y;
            As[(kq + 2) * 132 + m] = v.z; As[(kq + 3) * 132 + m] = v.w;
        }
#pragma unroll
        for (int rr = 0; rr < 3; rr++) {
            int u = t + rr * 256;
            int q = u >> 2, kq = (u & 3) << 2;
            float4 v = *reinterpret_cast<const float4*>(Bg + (size_t)q * P + k0 + kq);
            Bs[(kq + 0) * 196 + q] = v.x; Bs[(kq + 1) * 196 + q] = v.y;
            Bs[(kq + 2) * 196 + q] = v.z; Bs[(kq + 3) * 196 + q] = v.w;
        }
        __syncthreads();

#pragma unroll
        for (int kk = 0; kk < 16; kk++) {
            float a[8], b[12];
#pragma unroll
            for (int i = 0; i < 8; i++)  a[i] = As[kk * 132 + ty * 8 + i];
#pragma unroll
            for (int j = 0; j < 12; j++) b[j] = Bs[kk * 196 + tx * 12 + j];
#pragma unroll
            for (int i = 0; i < 8; i++)
#pragma unroll
                for (int j = 0; j < 12; j++)
                    c[i][j] = fmaf(a[i], b[j], c[i][j]);
        }
        __syncthreads();
    }

#pragma unroll
    for (int i = 0; i < 8; i++) {
        int m = m0 + ty * 8 + i;
#pragma unroll
        for (int j = 0; j < 12; j++) {
            int q = tx * 12 + j;
            int l = q / B1C, b1 = q - l * B1C;
            g_mid[(size_t)m * MIDW + l * R + kblk * B1C + b1] = __float_as_uint(c[i][j]);
        }
    }
#endif
}

// ---------------------------------------------------------------------------
// Stage 2: grid (128, 8, 4), 256 threads, dyn smem SMEM2
// ---------------------------------------------------------------------------
__global__ __launch_bounds__(256) void stage2_kernel(const float* __restrict__ w2,
                                                     const float* __restrict__ bias,
                                                     float* __restrict__ out)
{
#if HAS_TCGEN05
    extern __shared__ char smem_raw[];
    const uint32_t raw = smem_u32(smem_raw);
    const uint32_t base = (raw + 1023u) & ~1023u;
    char* sm = smem_raw + (base - raw);

    const int t = threadIdx.x;
    const int wid = t >> 5, lid = t & 31;
    const int m0 = blockIdx.x * BM;
    const int n0 = blockIdx.y * N2T;
    const int lblk = blockIdx.z;

    if (wid == 0) TC_ALLOC(base, 512);
    if (t == 0) { MBAR_INIT(base + 8, 1); MBAR_INIT(base + 16, 1); }
    __syncthreads();
    uint32_t tmem;
    asm volatile("ld.shared.b32 %0, [%1];" : "=r"(tmem) : "r"(base));

    const uint32_t* Ag = g_mid + (size_t)m0 * MIDW + lblk * R;
    const float*    Bg = w2 + (size_t)lblk * S * R + (size_t)n0 * R;

    int phase[2] = {0, 0};

    for (int c = 0; c < R / BK; ++c) {            // 3 chunks
        const int b = c & 1;
        if (c >= 2) { mbar_wait(base + 8 + b * 8, phase[b]); phase[b] ^= 1; }
        const int k0 = c * BK;
        char* Ahi = sm + HDR + b * S2_BUF;
        char* Alo = sm + HDR + b * S2_BUF + S2_A_LO;
        char* Bhi = sm + HDR + b * S2_BUF + S2_B_HI;
        char* Blo = sm + HDR + b * S2_BUF + S2_B_LO;

        for (int u = t; u < 128 * 32; u += 256) {
            int row = u >> 5, cp = u & 31;
            uint2 a = *reinterpret_cast<const uint2*>(Ag + (size_t)row * MIDW + k0 + 2 * cp);
            uint32_t hi = __byte_perm(a.x, a.y, 0x5410);
            uint32_t lo = __byte_perm(a.x, a.y, 0x7632);
            uint32_t off = sw128(row * 128 + cp * 4);
            *reinterpret_cast<uint32_t*>(Ahi + off) = hi;
            *reinterpret_cast<uint32_t*>(Alo + off) = lo;
        }
        for (int u = t; u < 128 * 32; u += 256) {
            int row = u >> 5, cp = u & 31;
            float2 v = *reinterpret_cast<const float2*>(Bg + (size_t)row * R + k0 + 2 * cp);
            __nv_bfloat162 h = __floats2bfloat162_rn(v.x, v.y);
            __nv_bfloat162 l = __floats2bfloat162_rn(v.x - __bfloat162float(h.x),
                                                     v.y - __bfloat162float(h.y));
            uint32_t off = sw128(row * 128 + cp * 4);
            *reinterpret_cast<uint32_t*>(Bhi + off) = *reinterpret_cast<uint32_t*>(&h);
            *reinterpret_cast<uint32_t*>(Blo + off) = *reinterpret_cast<uint32_t*>(&l);
        }
        FENCE_ASYNC();
        __syncthreads();

        if (wid == 0 && elect_one()) {
            uint64_t dAh = make_desc(base + HDR + b * S2_BUF);
            uint64_t dAl = make_desc(base + HDR + b * S2_BUF + S2_A_LO);
            uint64_t dBh = make_desc(base + HDR + b * S2_BUF + S2_B_HI);
            uint64_t dBl = make_desc(base + HDR + b * S2_BUF + S2_B_LO);
            bool first = (c == 0);
#pragma unroll
            for (int ks = 0; ks < 4; ks++)
                mma_f16_ss(tmem, dAh + ks * 2, dBh + ks * 2, IDESC2, !(first && ks == 0));
#pragma unroll
            for (int ks = 0; ks < 4; ks++)
                mma_f16_ss(tmem, dAh + ks * 2, dBl + ks * 2, IDESC2, true);
#pragma unroll
            for (int ks = 0; ks < 4; ks++)
                mma_f16_ss(tmem, dAl + ks * 2, dBh + ks * 2, IDESC2, true);
            TC_COMMIT(base + 8 + b * 8);
        }
    }

    mbar_wait(base + 8, phase[0]);
    mbar_wait(base + 16, phase[1]);
    TC_FENCE_AFTER();
    __syncthreads();

    float* stg = reinterpret_cast<float*>(sm + HDR);       // 128 x 129 f32
    if (wid < 4) {
        const int row = wid * 32 + lid;
#pragma unroll
        for (int cc = 0; cc < 4; ++cc) {
            uint32_t r32[32];
            TC_LD_X32(r32, tmem + cc * 32);
            TC_WAIT_LD();
#pragma unroll
            for (int j = 0; j < 32; ++j) stg[row * 129 + cc * 32 + j] = __uint_as_float(r32[j]);
        }
    }
    __syncthreads();

    const int col = t & 127;
    const int rhalf = t >> 7;                    // 0 or 1
    const float bv = bias[lblk * S + n0 + col];
    float* og = out + (size_t)m0 * OUT_F + lblk * S + n0 + col;
#pragma unroll 4
    for (int rr = 0; rr < 64; ++rr) {
        int row = rhalf * 64 + rr;
        og[(size_t)row * OUT_F] = stg[row * 129 + col] + bv;
    }

    __syncthreads();
    if (wid == 0) { TC_RELINQ(); TC_DEALLOC(tmem, 512); }
#else
    // ---- fp32 SIMT fallback: CTA computes 128 x 128, K=192 ----
    extern __shared__ char smem_raw[];
    float* As = reinterpret_cast<float*>(smem_raw);          // [16][132]
    float* Bs = As + 16 * 132;                               // [16][132]

    const int t = threadIdx.x;
    const int ty = t >> 4;           // rows of 8
    const int tx = t & 15;           // cols of 8
    const int m0 = blockIdx.x * BM;
    const int n0 = blockIdx.y * N2T;
    const int lblk = blockIdx.z;

    const float* Af = reinterpret_cast<const float*>(g_mid) + (size_t)m0 * MIDW + lblk * R;
    const float* Bg = w2 + (size_t)lblk * S * R + (size_t)n0 * R;

    float c[8][8];
#pragma unroll
    for (int i = 0; i < 8; i++)
#pragma unroll
        for (int j = 0; j < 8; j++) c[i][j] = 0.f;

    for (int k0 = 0; k0 < R; k0 += 16) {         // 12 chunks
#pragma unroll
        for (int rr = 0; rr < 2; rr++) {
            int u = t + rr * 256;
            int m = u >> 2, kq = (u & 3) << 2;
            float4 v = *reinterpret_cast<const float4*>(Af + (size_t)m * MIDW + k0 + kq);
            As[(kq + 0) * 132 + m] = v.x; As[(kq + 1) * 132 + m] = v.y;
            As[(kq + 2) * 132 + m] = v.z; As[(kq + 3) * 132 + m] = v.w;
        }
#pragma unroll
        for (int rr = 0; rr < 2; rr++) {
            int u = t + rr * 256;
            int q = u >> 2, kq = (u & 3) << 2;
            float4 v = *reinterpret_cast<const float4*>(Bg + (size_t)q * R + k0 + kq);
            Bs[(kq + 0) * 132 + q] = v.x; Bs[(kq + 1) * 132 + q] = v.y;
            Bs[(kq + 2) * 132 + q] = v.z; Bs[(kq + 3) * 132 + q] = v.w;
        }
        __syncthreads();

#pragma unroll
        for (int kk = 0; kk < 16; kk++) {
            float a[8], b[8];
#pragma unroll
            for (int i = 0; i < 8; i++) a[i] = As[kk * 132 + ty * 8 + i];
#pragma unroll
            for (int j = 0; j < 8; j++) b[j] = Bs[kk * 132 + tx * 8 + j];
#pragma unroll
            for (int i = 0; i < 8; i++)
#pragma unroll
                for (int j = 0; j < 8; j++)
                    c[i][j] = fmaf(a[i], b[j], c[i][j]);
        }
        __syncthreads();
    }

#pragma unroll
    for (int j = 0; j < 8; j++) {
        int sg = n0 + tx * 8 + j;
        float bv = bias[lblk * S + sg];
#pragma unroll
        for (int i = 0; i < 8; i++) {
            int m = m0 + ty * 8 + i;
            out[(size_t)m * OUT_F + lblk * S + sg] = c[i][j] + bv;
        }
    }
#endif
}

// ---------------------------------------------------------------------------
extern "C" void kernel_launch(void* const* d_in, const int* in_sizes, int n_in,
                              void* d_out, int out_size)
{
    const float* x    = (const float*)d_in[0];
    const float* w1   = (const float*)d_in[1];
    const float* w2   = (const float*)d_in[2];
    const float* bias = (const float*)d_in[3];
    float* out = (float*)d_out;

    static bool attr_set = false;
    if (!attr_set) {
        cudaFuncSetAttribute(stage1_kernel, cudaFuncAttributeMaxDynamicSharedMemorySize, SMEM1);
        cudaFuncSetAttribute(stage2_kernel, cudaFuncAttributeMaxDynamicSharedMemorySize, SMEM2);
        attr_set = true;
    }

    dim3 g1(BATCH / BM, NB1, 1);          // (128, 4)
    stage1_kernel<<<g1, 256, SMEM1>>>(x, w1);

    dim3 g2(BATCH / BM, S / N2T, NB2);    // (128, 8, 4)
    stage2_kernel<<<g2, 256, SMEM2>>>(w2, bias, out);
}

// round 7
// speedup vs baseline: 4.3152x; 2.7334x over previous
#include <cuda_runtime.h>
#include <cuda_bf16.h>
#include <cstdint>

// Monarch butterfly linear, tcgen05 bf16 split-precision (hi/lo) GEMMs.
// Weights are pre-converted once into bf16 hi/lo planes laid out in the exact
// swizzled smem image, so the GEMM kernels' B-fill is a pure uint4 memcpy.
// tcgen05 path only in arch-specific passes; plain compute_103 gets fp32 SIMT.

#if defined(__CUDA_ARCH__) && (defined(__CUDA_ARCH_FEAT_SM103_ALL) || defined(__CUDA_ARCH_FEAT_SM100_ALL))
#define HAS_TCGEN05 1
#else
#define HAS_TCGEN05 0
#endif

constexpr int BATCH = 16384;
constexpr int IN_F  = 4096;
constexpr int OUT_F = 4096;
constexpr int NB1 = 4, NB2 = 4, B1C = 48;
constexpr int P = 1024;   // stage1 K
constexpr int Q = 192;    // stage1 N
constexpr int R = 192;    // stage2 K
constexpr int S = 1024;   // stage2 N per l-block
constexpr int MIDW = NB2 * R;  // 768

constexpr int BM = 128;
constexpr int BK = 64;    // 64 bf16 cols = 128B = one SW128 atom row
constexpr int N2T = 256;  // stage2 N tile
constexpr int NTHREADS = 512;

// Scratch: intermediate packed (bf16 hi | bf16 lo) [48 MB] (fallback: fp32 bits)
__device__ uint32_t g_mid[(size_t)BATCH * MIDW];
// Pre-swizzled weight images (bf16 hi plane | lo plane per chunk), 3 MB each.
// w1: [kblk][chunk16][hi 24K | lo 24K]   w2: [lblk][ntile4][chunk3][hi 32K | lo 32K]
__device__ uint4 g_w1img[4 * 16 * 49152 / 16];
__device__ uint4 g_w2img[4 * 4 * 3 * 65536 / 16];

constexpr int HDR = 1024;
// stage1 buffer: Ahi 16K | Alo 16K | B(hi+lo) 48K = 80K
constexpr int S1_A_LO = 16384, S1_B = 32768, S1_BUF = 81920;
constexpr int SMEM1 = 1024 + HDR + 2 * S1_BUF;          // 165888
// stage2 buffer: Ahi 16K | Alo 16K | B(hi+lo) 64K = 96K
constexpr int S2_A_LO = 16384, S2_B = 32768, S2_BUF = 98304;
constexpr int SMEM2 = 1024 + HDR + 2 * S2_BUF;          // 198656

__host__ __device__ __forceinline__ uint32_t sw128(uint32_t byte_off) {
    return byte_off ^ ((byte_off >> 3) & 0x70);
}

// ---------------------------------------------------------------------------
// Weight pre-conversion kernels (plain CUDA, both compile variants)
// ---------------------------------------------------------------------------
__global__ __launch_bounds__(256) void conv_w1_kernel(const float* __restrict__ w1)
{
    int id = blockIdx.x * 256 + threadIdx.x;          // [0, 4*192*512)
    if (id >= 4 * 192 * 512) return;
    int k   = id / (192 * 512);
    int rem = id % (192 * 512);
    int row = rem / 512;
    int col = (rem % 512) * 2;
    float2 v = *reinterpret_cast<const float2*>(w1 + ((size_t)k * Q + row) * P + col);
    __nv_bfloat162 h = __floats2bfloat162_rn(v.x, v.y);
    __nv_bfloat162 l = __floats2bfloat162_rn(v.x - __bfloat162float(h.x),
                                             v.y - __bfloat162float(h.y));
    int chunk = col >> 6, cw = col & 63;
    char* img = (char*)g_w1img + (size_t)(k * 16 + chunk) * 49152;
    uint32_t off = sw128((uint32_t)(row * 128 + cw * 2));
    *reinterpret_cast<uint32_t*>(img + off)         = *reinterpret_cast<uint32_t*>(&h);
    *reinterpret_cast<uint32_t*>(img + 24576 + off) = *reinterpret_cast<uint32_t*>(&l);
}

__global__ __launch_bounds__(256) void conv_w2_kernel(const float* __restrict__ w2)
{
    int id = blockIdx.x * 256 + threadIdx.x;          // [0, 4*1024*96)
    if (id >= 4 * 1024 * 96) return;
    int l   = id / (1024 * 96);
    int rem = id % (1024 * 96);
    int s   = rem / 96;
    int col = (rem % 96) * 2;
    float2 v = *reinterpret_cast<const float2*>(w2 + ((size_t)l * S + s) * R + col);
    __nv_bfloat162 h = __floats2bfloat162_rn(v.x, v.y);
    __nv_bfloat162 lo = __floats2bfloat162_rn(v.x - __bfloat162float(h.x),
                                              v.y - __bfloat162float(h.y));
    int chunk = col >> 6, cw = col & 63;
    int ntile = s >> 8, rt = s & 255;
    char* img = (char*)g_w2img + (size_t)(((l * 4 + ntile) * 3) + chunk) * 65536;
    uint32_t off = sw128((uint32_t)(rt * 128 + cw * 2));
    *reinterpret_cast<uint32_t*>(img + off)         = *reinterpret_cast<uint32_t*>(&h);
    *reinterpret_cast<uint32_t*>(img + 32768 + off) = *reinterpret_cast<uint32_t*>(&lo);
}

#if HAS_TCGEN05
// ---------------------------------------------------------------------------
// PTX helpers (arch-specific pass only)
// ---------------------------------------------------------------------------
__device__ __forceinline__ uint32_t smem_u32(const void* p) {
    uint32_t a;
    asm("{ .reg .u64 t; cvta.to.shared.u64 t, %1; cvt.u32.u64 %0, t; }" : "=r"(a) : "l"(p));
    return a;
}
__device__ __forceinline__ bool elect_one() {
    uint32_t pred;
    asm volatile("{ .reg .pred p; elect.sync _|p, 0xFFFFFFFF; selp.b32 %0, 1, 0, p; }" : "=r"(pred));
    return pred != 0;
}
static constexpr uint64_t DESC_BASE_SW128 =
    (uint64_t(2)  << 61) | (uint64_t(1) << 46) | (uint64_t(64) << 32) | (uint64_t(1) << 16);
__device__ __forceinline__ uint64_t make_desc(uint32_t smem_addr) {
    return DESC_BASE_SW128 | ((uint64_t)(smem_addr >> 4) & 0x3FFF);
}

#define TC_ALLOC(smem_ptr_addr, n) \
    asm volatile("tcgen05.alloc.cta_group::1.sync.aligned.shared::cta.b32 [%0], %1;" \
                 :: "r"(smem_ptr_addr), "r"((uint32_t)(n)) : "memory")
#define TC_DEALLOC(tmem, n) \
    asm volatile("tcgen05.dealloc.cta_group::1.sync.aligned.b32 %0, %1;" :: "r"(tmem), "r"((uint32_t)(n)))
#define TC_RELINQ() \
    asm volatile("tcgen05.relinquish_alloc_permit.cta_group::1.sync.aligned;")
#define TC_COMMIT(mbar) \
    asm volatile("tcgen05.commit.cta_group::1.mbarrier::arrive::one.shared::cluster.b64 [%0];" \
                 :: "r"(mbar) : "memory")
#define TC_FENCE_AFTER()  asm volatile("tcgen05.fence::after_thread_sync;" ::: "memory")
#define TC_WAIT_LD()      asm volatile("tcgen05.wait::ld.sync.aligned;" ::: "memory")
#define FENCE_ASYNC()     asm volatile("fence.proxy.async.shared::cta;" ::: "memory")
#define MBAR_INIT(mbar, n) \
    asm volatile("mbarrier.init.shared.b64 [%0], %1;" :: "r"(mbar), "r"((uint32_t)(n)) : "memory")

__device__ __forceinline__ void mbar_wait(uint32_t mbar, int parity) {
    uint32_t done;
    asm volatile("{ .reg .pred p; mbarrier.try_wait.parity.acquire.cta.shared::cta.b64 p, [%1], %2; selp.b32 %0, 1, 0, p; }"
                 : "=r"(done) : "r"(mbar), "r"((uint32_t)parity) : "memory");
    if (!done) {
        asm volatile(
            "{ .reg .pred P1;\n"
            "WAIT_%=: mbarrier.try_wait.parity.acquire.cta.shared::cta.b64 P1, [%0], %1, 0x989680;\n"
            "@P1 bra.uni DONE_%=;\n"
            "bra.uni WAIT_%=;\n"
            "DONE_%=: }"
            :: "r"(mbar), "r"((uint32_t)parity) : "memory");
    }
}

__device__ __forceinline__ void mma_f16_ss(uint32_t d_tmem, uint64_t a_desc, uint64_t b_desc,
                                           uint32_t idesc, bool acc) {
    uint32_t en = acc ? 1u : 0u;
    asm volatile(
        "{ .reg .pred p; setp.ne.u32 p, %4, 0;\n"
        "tcgen05.mma.cta_group::1.kind::f16 [%0], %1, %2, %3, {%5, %5, %5, %5}, p; }"
        :: "r"(d_tmem), "l"(a_desc), "l"(b_desc), "r"(idesc), "r"(en), "r"(0u)
        : "memory");
}

#define TC_LD_X32(r, addr) \
    asm volatile("tcgen05.ld.sync.aligned.32x32b.x32.b32 " \
        "{%0,%1,%2,%3,%4,%5,%6,%7,%8,%9,%10,%11,%12,%13,%14,%15," \
        "%16,%17,%18,%19,%20,%21,%22,%23,%24,%25,%26,%27,%28,%29,%30,%31}, [%32];" \
        : "=r"((r)[0]),"=r"((r)[1]),"=r"((r)[2]),"=r"((r)[3]),"=r"((r)[4]),"=r"((r)[5]),"=r"((r)[6]),"=r"((r)[7]), \
          "=r"((r)[8]),"=r"((r)[9]),"=r"((r)[10]),"=r"((r)[11]),"=r"((r)[12]),"=r"((r)[13]),"=r"((r)[14]),"=r"((r)[15]), \
          "=r"((r)[16]),"=r"((r)[17]),"=r"((r)[18]),"=r"((r)[19]),"=r"((r)[20]),"=r"((r)[21]),"=r"((r)[22]),"=r"((r)[23]), \
          "=r"((r)[24]),"=r"((r)[25]),"=r"((r)[26]),"=r"((r)[27]),"=r"((r)[28]),"=r"((r)[29]),"=r"((r)[30]),"=r"((r)[31]) \
        : "r"(addr))

constexpr uint32_t IDESC1 = (8u << 24) | ((Q   / 8u) << 17) | (1u << 10) | (1u << 7) | (1u << 4); // M=128,N=192
constexpr uint32_t IDESC2 = (8u << 24) | ((N2T / 8u) << 17) | (1u << 10) | (1u << 7) | (1u << 4); // M=128,N=256

__device__ __forceinline__ uint32_t pack_hi(float a, float b) {
    __nv_bfloat162 h = __floats2bfloat162_rn(a, b);
    return *reinterpret_cast<uint32_t*>(&h);
}
__device__ __forceinline__ uint32_t pack_lo(float a, float b, uint32_t hibits) {
    __nv_bfloat162 h = *reinterpret_cast<__nv_bfloat162*>(&hibits);
    __nv_bfloat162 l = __floats2bfloat162_rn(a - __bfloat162float(h.x),
                                             b - __bfloat162float(h.y));
    return *reinterpret_cast<uint32_t*>(&l);
}
#endif  // HAS_TCGEN05

// ---------------------------------------------------------------------------
// Stage 1: grid (128, 4), 512 threads, dyn smem SMEM1
// ---------------------------------------------------------------------------
__global__ __launch_bounds__(NTHREADS) void stage1_kernel(const float* __restrict__ x,
                                                          const float* __restrict__ w1)
{
#if HAS_TCGEN05
    extern __shared__ char smem_raw[];
    const uint32_t raw = smem_u32(smem_raw);
    const uint32_t base = (raw + 1023u) & ~1023u;
    char* sm = smem_raw + (base - raw);

    const int t = threadIdx.x;
    const int wid = t >> 5, lid = t & 31;
    const int m0 = blockIdx.x * BM;
    const int kblk = blockIdx.y;

    if (wid == 0) TC_ALLOC(base, 512);
    if (t == 0) { MBAR_INIT(base + 8, 1); MBAR_INIT(base + 16, 1); }
    __syncthreads();
    uint32_t tmem;
    asm volatile("ld.shared.b32 %0, [%1];" : "=r"(tmem) : "r"(base));

    const float* Ag = x + (size_t)m0 * IN_F + (size_t)kblk * P;

    // A-fill addressing: thread covers row = t>>2, cols [seg*16, seg*16+16)
    const int arow = t >> 2, aseg = t & 3;
    const uint32_t a_off0 = sw128((uint32_t)(arow * 128 + aseg * 32));
    const uint32_t a_off1 = sw128((uint32_t)(arow * 128 + aseg * 32 + 16));
    const float* a_src = Ag + (size_t)arow * IN_F + aseg * 16;

    int phase[2] = {0, 0};

    for (int c = 0; c < P / BK; ++c) {            // 16 chunks
        const int b = c & 1;
        if (c >= 2) { mbar_wait(base + 8 + b * 8, phase[b]); phase[b] ^= 1; }
        char* Ahi = sm + HDR + b * S1_BUF;
        char* Alo = Ahi + S1_A_LO;
        uint4* Bd = reinterpret_cast<uint4*>(sm + HDR + b * S1_BUF + S1_B);

        // B tile: pure 48KB memcpy from pre-swizzled image
        {
            const uint4* src = g_w1img + (size_t)(kblk * 16 + c) * 3072;
#pragma unroll
            for (int u = 0; u < 6; ++u) Bd[t + u * NTHREADS] = src[t + u * NTHREADS];
        }
        // A tile: 4 float4 loads -> split -> 2+2 STS.128
        {
            const float4* s = reinterpret_cast<const float4*>(a_src + (size_t)c * BK);
            float4 a0 = s[0], a1 = s[1], a2 = s[2], a3 = s[3];
            uint4 h0, h1, l0, l1;
            h0.x = pack_hi(a0.x, a0.y); l0.x = pack_lo(a0.x, a0.y, h0.x);
            h0.y = pack_hi(a0.z, a0.w); l0.y = pack_lo(a0.z, a0.w, h0.y);
            h0.z = pack_hi(a1.x, a1.y); l0.z = pack_lo(a1.x, a1.y, h0.z);
            h0.w = pack_hi(a1.z, a1.w); l0.w = pack_lo(a1.z, a1.w, h0.w);
            h1.x = pack_hi(a2.x, a2.y); l1.x = pack_lo(a2.x, a2.y, h1.x);
            h1.y = pack_hi(a2.z, a2.w); l1.y = pack_lo(a2.z, a2.w, h1.y);
            h1.z = pack_hi(a3.x, a3.y); l1.z = pack_lo(a3.x, a3.y, h1.z);
            h1.w = pack_hi(a3.z, a3.w); l1.w = pack_lo(a3.z, a3.w, h1.w);
            *reinterpret_cast<uint4*>(Ahi + a_off0) = h0;
            *reinterpret_cast<uint4*>(Ahi + a_off1) = h1;
            *reinterpret_cast<uint4*>(Alo + a_off0) = l0;
            *reinterpret_cast<uint4*>(Alo + a_off1) = l1;
        }
        FENCE_ASYNC();
        __syncthreads();

        if (wid == 0 && elect_one()) {
            uint64_t dAh = make_desc(base + HDR + b * S1_BUF);
            uint64_t dAl = make_desc(base + HDR + b * S1_BUF + S1_A_LO);
            uint64_t dBh = make_desc(base + HDR + b * S1_BUF + S1_B);
            uint64_t dBl = make_desc(base + HDR + b * S1_BUF + S1_B + 24576);
            bool first = (c == 0);
#pragma unroll
            for (int ks = 0; ks < 4; ks++)
                mma_f16_ss(tmem, dAh + ks * 2, dBh + ks * 2, IDESC1, !(first && ks == 0));
#pragma unroll
            for (int ks = 0; ks < 4; ks++)
                mma_f16_ss(tmem, dAh + ks * 2, dBl + ks * 2, IDESC1, true);
#pragma unroll
            for (int ks = 0; ks < 4; ks++)
                mma_f16_ss(tmem, dAl + ks * 2, dBh + ks * 2, IDESC1, true);
            TC_COMMIT(base + 8 + b * 8);
        }
    }

    mbar_wait(base + 8, phase[0]);
    mbar_wait(base + 16, phase[1]);
    TC_FENCE_AFTER();
    __syncthreads();

    float* stg = reinterpret_cast<float*>(sm + HDR);       // 128 x 193 f32
    if (wid < 4) {
        const int row = wid * 32 + lid;
#pragma unroll
        for (int cc = 0; cc < 6; ++cc) {
            uint32_t r32[32];
            TC_LD_X32(r32, tmem + cc * 32);
            TC_WAIT_LD();
#pragma unroll
            for (int j = 0; j < 32; ++j) stg[row * 193 + cc * 32 + j] = __uint_as_float(r32[j]);
        }
    }
    __syncthreads();

    for (int u = t; u < 128 * 192; u += NTHREADS) {
        int r = u / 192, q = u - r * 192;
        int l = q / B1C, b1 = q - l * B1C;
        float f = stg[r * 193 + q];
        __nv_bfloat16 h = __float2bfloat16_rn(f);
        __nv_bfloat16 lo = __float2bfloat16_rn(f - __bfloat162float(h));
        uint32_t packed = (uint32_t)__bfloat16_as_ushort(h) |
                          ((uint32_t)__bfloat16_as_ushort(lo) << 16);
        g_mid[(size_t)(m0 + r) * MIDW + l * R + kblk * B1C + b1] = packed;
    }

    __syncthreads();
    if (wid == 0) { TC_RELINQ(); TC_DEALLOC(tmem, 512); }
#else
    // ---- fp32 SIMT fallback: CTA 128 x 192, K=1024, 512 threads ----
    extern __shared__ char smem_raw[];
    float* As = reinterpret_cast<float*>(smem_raw);          // [16][132]
    float* Bs = As + 16 * 132;                               // [16][196]

    const int t = threadIdx.x;
    const int ty = t >> 5;           // 0..15 rows of 8
    const int tx = t & 31;           // 0..31 cols of 6
    const int m0 = blockIdx.x * BM;
    const int kblk = blockIdx.y;

    const float* Ag = x  + (size_t)m0 * IN_F + (size_t)kblk * P;
    const float* Bg = w1 + (size_t)kblk * Q * P;

    float c[8][6];
#pragma unroll
    for (int i = 0; i < 8; i++)
#pragma unroll
        for (int j = 0; j < 6; j++) c[i][j] = 0.f;

    for (int k0 = 0; k0 < P; k0 += 16) {
        {
            int u = t;                                    // 512 float4 exactly
            int m = u >> 2, kq = (u & 3) << 2;
            float4 v = *reinterpret_cast<const float4*>(Ag + (size_t)m * IN_F + k0 + kq);
            As[(kq + 0) * 132 + m] = v.x; As[(kq + 1) * 132 + m] = v.y;
            As[(kq + 2) * 132 + m] = v.z; As[(kq + 3) * 132 + m] = v.w;
        }
        for (int u = t; u < 768; u += NTHREADS) {
            int q = u >> 2, kq = (u & 3) << 2;
            float4 v = *reinterpret_cast<const float4*>(Bg + (size_t)q * P + k0 + kq);
            Bs[(kq + 0) * 196 + q] = v.x; Bs[(kq + 1) * 196 + q] = v.y;
            Bs[(kq + 2) * 196 + q] = v.z; Bs[(kq + 3) * 196 + q] = v.w;
        }
        __syncthreads();

#pragma unroll
        for (int kk = 0; kk < 16; kk++) {
            float a[8], bb[6];
#pragma unroll
            for (int i = 0; i < 8; i++) a[i] = As[kk * 132 + ty * 8 + i];
#pragma unroll
            for (int j = 0; j < 6; j++) bb[j] = Bs[kk * 196 + tx * 6 + j];
#pragma unroll
            for (int i = 0; i < 8; i++)
#pragma unroll
                for (int j = 0; j < 6; j++)
                    c[i][j] = fmaf(a[i], bb[j], c[i][j]);
        }
        __syncthreads();
    }

#pragma unroll
    for (int i = 0; i < 8; i++) {
        int m = m0 + ty * 8 + i;
#pragma unroll
        for (int j = 0; j < 6; j++) {
            int q = tx * 6 + j;
            int l = q / B1C, b1 = q - l * B1C;
            g_mid[(size_t)m * MIDW + l * R + kblk * B1C + b1] = __float_as_uint(c[i][j]);
        }
    }
#endif
}

// ---------------------------------------------------------------------------
// Stage 2: grid (128, 4, 4), 512 threads, dyn smem SMEM2
// ---------------------------------------------------------------------------
__global__ __launch_bounds__(NTHREADS) void stage2_kernel(const float* __restrict__ w2,
                                                          const float* __restrict__ bias,
                                                          float* __restrict__ out)
{
#if HAS_TCGEN05
    extern __shared__ char smem_raw[];
    const uint32_t raw = smem_u32(smem_raw);
    const uint32_t base = (raw + 1023u) & ~1023u;
    char* sm = smem_raw + (base - raw);

    const int t = threadIdx.x;
    const int wid = t >> 5, lid = t & 31;
    const int m0 = blockIdx.x * BM;
    const int n0 = blockIdx.y * N2T;
    const int lblk = blockIdx.z;

    if (wid == 0) TC_ALLOC(base, 512);
    if (t == 0) { MBAR_INIT(base + 8, 1); MBAR_INIT(base + 16, 1); }
    __syncthreads();
    uint32_t tmem;
    asm volatile("ld.shared.b32 %0, [%1];" : "=r"(tmem) : "r"(base));

    const uint32_t* Ag = g_mid + (size_t)m0 * MIDW + lblk * R;

    const int arow = t >> 2, aseg = t & 3;       // cols [aseg*16, +16)
    const uint32_t a_off0 = sw128((uint32_t)(arow * 128 + aseg * 32));
    const uint32_t a_off1 = sw128((uint32_t)(arow * 128 + aseg * 32 + 16));
    const uint32_t* a_src = Ag + (size_t)arow * MIDW + aseg * 16;

    int phase[2] = {0, 0};

    for (int c = 0; c < R / BK; ++c) {            // 3 chunks
        const int b = c & 1;
        if (c >= 2) { mbar_wait(base + 8 + b * 8, phase[b]); phase[b] ^= 1; }
        char* Ahi = sm + HDR + b * S2_BUF;
        char* Alo = Ahi + S2_A_LO;
        uint4* Bd = reinterpret_cast<uint4*>(sm + HDR + b * S2_BUF + S2_B);

        // B tile: pure 64KB memcpy from pre-swizzled image
        {
            const uint4* src = g_w2img + (size_t)(((lblk * 4 + (n0 >> 8)) * 3) + c) * 4096;
#pragma unroll
            for (int u = 0; u < 8; ++u) Bd[t + u * NTHREADS] = src[t + u * NTHREADS];
        }
        // A tile: 4 uint4 loads of packed pairs -> PRMT split -> 2+2 STS.128
        {
            const uint4* s = reinterpret_cast<const uint4*>(a_src + (size_t)c * BK);
            uint4 p0 = s[0], p1 = s[1], p2 = s[2], p3 = s[3];
            uint4 h0, h1, l0, l1;
            h0.x = __byte_perm(p0.x, p0.y, 0x5410); l0.x = __byte_perm(p0.x, p0.y, 0x7632);
            h0.y = __byte_perm(p0.z, p0.w, 0x5410); l0.y = __byte_perm(p0.z, p0.w, 0x7632);
            h0.z = __byte_perm(p1.x, p1.y, 0x5410); l0.z = __byte_perm(p1.x, p1.y, 0x7632);
            h0.w = __byte_perm(p1.z, p1.w, 0x5410); l0.w = __byte_perm(p1.z, p1.w, 0x7632);
            h1.x = __byte_perm(p2.x, p2.y, 0x5410); l1.x = __byte_perm(p2.x, p2.y, 0x7632);
            h1.y = __byte_perm(p2.z, p2.w, 0x5410); l1.y = __byte_perm(p2.z, p2.w, 0x7632);
            h1.z = __byte_perm(p3.x, p3.y, 0x5410); l1.z = __byte_perm(p3.x, p3.y, 0x7632);
            h1.w = __byte_perm(p3.z, p3.w, 0x5410); l1.w = __byte_perm(p3.z, p3.w, 0x7632);
            *reinterpret_cast<uint4*>(Ahi + a_off0) = h0;
            *reinterpret_cast<uint4*>(Ahi + a_off1) = h1;
            *reinterpret_cast<uint4*>(Alo + a_off0) = l0;
            *reinterpret_cast<uint4*>(Alo + a_off1) = l1;
        }
        FENCE_ASYNC();
        __syncthreads();

        if (wid == 0 && elect_one()) {
            uint64_t dAh = make_desc(base + HDR + b * S2_BUF);
            uint64_t dAl = make_desc(base + HDR + b * S2_BUF + S2_A_LO);
            uint64_t dBh = make_desc(base + HDR + b * S2_BUF + S2_B);
            uint64_t dBl = make_desc(base + HDR + b * S2_BUF + S2_B + 32768);
            bool first = (c == 0);
#pragma unroll
            for (int ks = 0; ks < 4; ks++)
                mma_f16_ss(tmem, dAh + ks * 2, dBh + ks * 2, IDESC2, !(first && ks == 0));
#pragma unroll
            for (int ks = 0; ks < 4; ks++)
                mma_f16_ss(tmem, dAh + ks * 2, dBl + ks * 2, IDESC2, true);
#pragma unroll
            for (int ks = 0; ks < 4; ks++)
                mma_f16_ss(tmem, dAl + ks * 2, dBh + ks * 2, IDESC2, true);
            TC_COMMIT(base + 8 + b * 8);
        }
    }

    mbar_wait(base + 8, phase[0]);
    mbar_wait(base + 16, phase[1]);
    TC_FENCE_AFTER();
    __syncthreads();

    float* stg = reinterpret_cast<float*>(sm + HDR);       // 128 x 257 f32
    if (wid < 4) {
        const int row = wid * 32 + lid;
#pragma unroll
        for (int cc = 0; cc < 8; ++cc) {
            uint32_t r32[32];
            TC_LD_X32(r32, tmem + cc * 32);
            TC_WAIT_LD();
#pragma unroll
            for (int j = 0; j < 32; ++j) stg[row * 257 + cc * 32 + j] = __uint_as_float(r32[j]);
        }
    }
    __syncthreads();

    const int col = t & 255;
    const int rhalf = t >> 8;                    // 0 or 1
    const float bv = bias[lblk * S + n0 + col];
    float* og = out + (size_t)m0 * OUT_F + lblk * S + n0 + col;
#pragma unroll 4
    for (int rr = 0; rr < 64; ++rr) {
        int row = rhalf * 64 + rr;
        og[(size_t)row * OUT_F] = stg[row * 257 + col] + bv;
    }

    __syncthreads();
    if (wid == 0) { TC_RELINQ(); TC_DEALLOC(tmem, 512); }
#else
    // ---- fp32 SIMT fallback: CTA 128 x 256, K=192, 512 threads ----
    extern __shared__ char smem_raw[];
    float* As = reinterpret_cast<float*>(smem_raw);          // [16][132]
    float* Bs = As + 16 * 132;                               // [16][260]

    const int t = threadIdx.x;
    const int ty = t >> 5;           // rows of 8 (16 groups)
    const int tx = t & 31;           // cols of 8 (32 groups)
    const int m0 = blockIdx.x * BM;
    const int n0 = blockIdx.y * N2T;
    const int lblk = blockIdx.z;

    const float* Af = reinterpret_cast<const float*>(g_mid) + (size_t)m0 * MIDW + lblk * R;
    const float* Bg = w2 + (size_t)lblk * S * R + (size_t)n0 * R;

    float c[8][8];
#pragma unroll
    for (int i = 0; i < 8; i++)
#pragma unroll
        for (int j = 0; j < 8; j++) c[i][j] = 0.f;

    for (int k0 = 0; k0 < R; k0 += 16) {         // 12 chunks
        {
            int u = t;                                    // 512 float4 exactly
            int m = u >> 2, kq = (u & 3) << 2;
            float4 v = *reinterpret_cast<const float4*>(Af + (size_t)m * MIDW + k0 + kq);
            As[(kq + 0) * 132 + m] = v.x; As[(kq + 1) * 132 + m] = v.y;
            As[(kq + 2) * 132 + m] = v.z; As[(kq + 3) * 132 + m] = v.w;
        }
        for (int u = t; u < 1024; u += NTHREADS) {
            int q = u >> 2, kq = (u & 3) << 2;
            float4 v = *reinterpret_cast<const float4*>(Bg + (size_t)q * R + k0 + kq);
            Bs[(kq + 0) * 260 + q] = v.x; Bs[(kq + 1) * 260 + q] = v.y;
            Bs[(kq + 2) * 260 + q] = v.z; Bs[(kq + 3) * 260 + q] = v.w;
        }
        __syncthreads();

#pragma unroll
        for (int kk = 0; kk < 16; kk++) {
            float a[8], bb[8];
#pragma unroll
            for (int i = 0; i < 8; i++) a[i] = As[kk * 132 + ty * 8 + i];
#pragma unroll
            for (int j = 0; j < 8; j++) bb[j] = Bs[kk * 260 + tx * 8 + j];
#pragma unroll
            for (int i = 0; i < 8; i++)
#pragma unroll
                for (int j = 0; j < 8; j++)
                    c[i][j] = fmaf(a[i], bb[j], c[i][j]);
        }
        __syncthreads();
    }

#pragma unroll
    for (int j = 0; j < 8; j++) {
        int sg = n0 + tx * 8 + j;
        float bv = bias[lblk * S + sg];
#pragma unroll
        for (int i = 0; i < 8; i++) {
            int m = m0 + ty * 8 + i;
            out[(size_t)m * OUT_F + lblk * S + sg] = c[i][j] + bv;
        }
    }
#endif
}

// ---------------------------------------------------------------------------
extern "C" void kernel_launch(void* const* d_in, const int* in_sizes, int n_in,
                              void* d_out, int out_size)
{
    const float* x    = (const float*)d_in[0];
    const float* w1   = (const float*)d_in[1];
    const float* w2   = (const float*)d_in[2];
    const float* bias = (const float*)d_in[3];
    float* out = (float*)d_out;

    // Unconditional (no static guards): identical work on every call.
    cudaFuncSetAttribute(stage1_kernel, cudaFuncAttributeMaxDynamicSharedMemorySize, SMEM1);
    cudaFuncSetAttribute(stage2_kernel, cudaFuncAttributeMaxDynamicSharedMemorySize, SMEM2);

    conv_w1_kernel<<<1536, 256>>>(w1);
    conv_w2_kernel<<<1536, 256>>>(w2);

    dim3 g1(BATCH / BM, NB1, 1);          // (128, 4)
    stage1_kernel<<<g1, NTHREADS, SMEM1>>>(x, w1);

    dim3 g2(BATCH / BM, S / N2T, NB2);    // (128, 4, 4)
    stage2_kernel<<<g2, NTHREADS, SMEM2>>>(w2, bias, out);
}

// round 8
// speedup vs baseline: 4.6511x; 1.0778x over previous
#include <cuda_runtime.h>
#include <cuda_bf16.h>
#include <cstdint>

// Monarch butterfly linear, tcgen05 bf16 split-precision (hi/lo) GEMMs.
// Weights pre-converted once into bf16 hi/lo planes in the exact swizzled smem
// image; B tiles stream into smem via cp.async.bulk (single elected thread,
// mbarrier completion) while all threads fill/convert the A tile.
// tcgen05 path only in arch-specific passes; plain compute_103 gets fp32 SIMT.

#if defined(__CUDA_ARCH__) && (defined(__CUDA_ARCH_FEAT_SM103_ALL) || defined(__CUDA_ARCH_FEAT_SM100_ALL))
#define HAS_TCGEN05 1
#else
#define HAS_TCGEN05 0
#endif

constexpr int BATCH = 16384;
constexpr int IN_F  = 4096;
constexpr int OUT_F = 4096;
constexpr int NB1 = 4, NB2 = 4, B1C = 48;
constexpr int P = 1024;   // stage1 K
constexpr int Q = 192;    // stage1 N
constexpr int R = 192;    // stage2 K
constexpr int S = 1024;   // stage2 N per l-block
constexpr int MIDW = NB2 * R;  // 768

constexpr int BM = 128;
constexpr int BK = 64;    // 64 bf16 cols = 128B = one SW128 atom row
constexpr int N2T = 256;  // stage2 N tile
constexpr int NTHREADS = 512;

// Scratch: intermediate packed (bf16 hi | bf16 lo) [48 MB] (fallback: fp32 bits)
__device__ uint32_t g_mid[(size_t)BATCH * MIDW];
// Pre-swizzled weight images (bf16 hi plane | lo plane per chunk), 3 MB each.
// w1: [kblk][chunk16][hi 24K | lo 24K]   w2: [lblk][ntile4][chunk3][hi 32K | lo 32K]
__device__ uint4 g_w1img[4 * 16 * 49152 / 16];
__device__ uint4 g_w2img[4 * 4 * 3 * 65536 / 16];

constexpr int HDR = 1024;
// stage1 buffer: Ahi 16K | Alo 16K | B(hi+lo) 48K = 80K
constexpr int S1_A_LO = 16384, S1_B = 32768, S1_BUF = 81920;
constexpr int S1_B_BYTES = 49152;
constexpr int SMEM1 = 1024 + HDR + 2 * S1_BUF;          // 165888
// stage2 buffer: Ahi 16K | Alo 16K | B(hi+lo) 64K = 96K
constexpr int S2_A_LO = 16384, S2_B = 32768, S2_BUF = 98304;
constexpr int S2_B_BYTES = 65536;
constexpr int SMEM2 = 1024 + HDR + 2 * S2_BUF;          // 198656

__host__ __device__ __forceinline__ uint32_t sw128(uint32_t byte_off) {
    return byte_off ^ ((byte_off >> 3) & 0x70);
}

// ---------------------------------------------------------------------------
// Weight pre-conversion kernels (plain CUDA, both compile variants)
// ---------------------------------------------------------------------------
__global__ __launch_bounds__(256) void conv_w1_kernel(const float* __restrict__ w1)
{
    int id = blockIdx.x * 256 + threadIdx.x;          // [0, 4*192*512)
    if (id >= 4 * 192 * 512) return;
    int k   = id / (192 * 512);
    int rem = id % (192 * 512);
    int row = rem / 512;
    int col = (rem % 512) * 2;
    float2 v = *reinterpret_cast<const float2*>(w1 + ((size_t)k * Q + row) * P + col);
    __nv_bfloat162 h = __floats2bfloat162_rn(v.x, v.y);
    __nv_bfloat162 l = __floats2bfloat162_rn(v.x - __bfloat162float(h.x),
                                             v.y - __bfloat162float(h.y));
    int chunk = col >> 6, cw = col & 63;
    char* img = (char*)g_w1img + (size_t)(k * 16 + chunk) * 49152;
    uint32_t off = sw128((uint32_t)(row * 128 + cw * 2));
    *reinterpret_cast<uint32_t*>(img + off)         = *reinterpret_cast<uint32_t*>(&h);
    *reinterpret_cast<uint32_t*>(img + 24576 + off) = *reinterpret_cast<uint32_t*>(&l);
}

__global__ __launch_bounds__(256) void conv_w2_kernel(const float* __restrict__ w2)
{
    int id = blockIdx.x * 256 + threadIdx.x;          // [0, 4*1024*96)
    if (id >= 4 * 1024 * 96) return;
    int l   = id / (1024 * 96);
    int rem = id % (1024 * 96);
    int s   = rem / 96;
    int col = (rem % 96) * 2;
    float2 v = *reinterpret_cast<const float2*>(w2 + ((size_t)l * S + s) * R + col);
    __nv_bfloat162 h = __floats2bfloat162_rn(v.x, v.y);
    __nv_bfloat162 lo = __floats2bfloat162_rn(v.x - __bfloat162float(h.x),
                                              v.y - __bfloat162float(h.y));
    int chunk = col >> 6, cw = col & 63;
    int ntile = s >> 8, rt = s & 255;
    char* img = (char*)g_w2img + (size_t)(((l * 4 + ntile) * 3) + chunk) * 65536;
    uint32_t off = sw128((uint32_t)(rt * 128 + cw * 2));
    *reinterpret_cast<uint32_t*>(img + off)         = *reinterpret_cast<uint32_t*>(&h);
    *reinterpret_cast<uint32_t*>(img + 32768 + off) = *reinterpret_cast<uint32_t*>(&lo);
}

#if HAS_TCGEN05
// ---------------------------------------------------------------------------
// PTX helpers (arch-specific pass only)
// ---------------------------------------------------------------------------
__device__ __forceinline__ uint32_t smem_u32(const void* p) {
    uint32_t a;
    asm("{ .reg .u64 t; cvta.to.shared.u64 t, %1; cvt.u32.u64 %0, t; }" : "=r"(a) : "l"(p));
    return a;
}
__device__ __forceinline__ bool elect_one() {
    uint32_t pred;
    asm volatile("{ .reg .pred p; elect.sync _|p, 0xFFFFFFFF; selp.b32 %0, 1, 0, p; }" : "=r"(pred));
    return pred != 0;
}
static constexpr uint64_t DESC_BASE_SW128 =
    (uint64_t(2)  << 61) | (uint64_t(1) << 46) | (uint64_t(64) << 32) | (uint64_t(1) << 16);
__device__ __forceinline__ uint64_t make_desc(uint32_t smem_addr) {
    return DESC_BASE_SW128 | ((uint64_t)(smem_addr >> 4) & 0x3FFF);
}

#define TC_ALLOC(smem_ptr_addr, n) \
    asm volatile("tcgen05.alloc.cta_group::1.sync.aligned.shared::cta.b32 [%0], %1;" \
                 :: "r"(smem_ptr_addr), "r"((uint32_t)(n)) : "memory")
#define TC_DEALLOC(tmem, n) \
    asm volatile("tcgen05.dealloc.cta_group::1.sync.aligned.b32 %0, %1;" :: "r"(tmem), "r"((uint32_t)(n)))
#define TC_RELINQ() \
    asm volatile("tcgen05.relinquish_alloc_permit.cta_group::1.sync.aligned;")
#define TC_COMMIT(mbar) \
    asm volatile("tcgen05.commit.cta_group::1.mbarrier::arrive::one.shared::cluster.b64 [%0];" \
                 :: "r"(mbar) : "memory")
#define TC_FENCE_AFTER()  asm volatile("tcgen05.fence::after_thread_sync;" ::: "memory")
#define TC_WAIT_LD()      asm volatile("tcgen05.wait::ld.sync.aligned;" ::: "memory")
#define FENCE_ASYNC()     asm volatile("fence.proxy.async.shared::cta;" ::: "memory")
#define MBAR_INIT(mbar, n) \
    asm volatile("mbarrier.init.shared.b64 [%0], %1;" :: "r"(mbar), "r"((uint32_t)(n)) : "memory")
#define MBAR_EXPECT_TX(mbar, bytes) \
    asm volatile("mbarrier.arrive.expect_tx.shared.b64 _, [%0], %1;" \
                 :: "r"(mbar), "r"((uint32_t)(bytes)) : "memory")
#define BULK_CP(dst_smem, src_gmem, bytes, mbar) \
    asm volatile("cp.async.bulk.shared::cta.global.mbarrier::complete_tx::bytes [%0], [%1], %2, [%3];" \
                 :: "r"(dst_smem), "l"(src_gmem), "r"((uint32_t)(bytes)), "r"(mbar) : "memory")

__device__ __forceinline__ void mbar_wait(uint32_t mbar, int parity) {
    uint32_t done;
    asm volatile("{ .reg .pred p; mbarrier.try_wait.parity.acquire.cta.shared::cta.b64 p, [%1], %2; selp.b32 %0, 1, 0, p; }"
                 : "=r"(done) : "r"(mbar), "r"((uint32_t)parity) : "memory");
    if (!done) {
        asm volatile(
            "{ .reg .pred P1;\n"
            "WAIT_%=: mbarrier.try_wait.parity.acquire.cta.shared::cta.b64 P1, [%0], %1, 0x989680;\n"
            "@P1 bra.uni DONE_%=;\n"
            "bra.uni WAIT_%=;\n"
            "DONE_%=: }"
            :: "r"(mbar), "r"((uint32_t)parity) : "memory");
    }
}

__device__ __forceinline__ void mma_f16_ss(uint32_t d_tmem, uint64_t a_desc, uint64_t b_desc,
                                           uint32_t idesc, bool acc) {
    uint32_t en = acc ? 1u : 0u;
    asm volatile(
        "{ .reg .pred p; setp.ne.u32 p, %4, 0;\n"
        "tcgen05.mma.cta_group::1.kind::f16 [%0], %1, %2, %3, {%5, %5, %5, %5}, p; }"
        :: "r"(d_tmem), "l"(a_desc), "l"(b_desc), "r"(idesc), "r"(en), "r"(0u)
        : "memory");
}

#define TC_LD_X32(r, addr) \
    asm volatile("tcgen05.ld.sync.aligned.32x32b.x32.b32 " \
        "{%0,%1,%2,%3,%4,%5,%6,%7,%8,%9,%10,%11,%12,%13,%14,%15," \
        "%16,%17,%18,%19,%20,%21,%22,%23,%24,%25,%26,%27,%28,%29,%30,%31}, [%32];" \
        : "=r"((r)[0]),"=r"((r)[1]),"=r"((r)[2]),"=r"((r)[3]),"=r"((r)[4]),"=r"((r)[5]),"=r"((r)[6]),"=r"((r)[7]), \
          "=r"((r)[8]),"=r"((r)[9]),"=r"((r)[10]),"=r"((r)[11]),"=r"((r)[12]),"=r"((r)[13]),"=r"((r)[14]),"=r"((r)[15]), \
          "=r"((r)[16]),"=r"((r)[17]),"=r"((r)[18]),"=r"((r)[19]),"=r"((r)[20]),"=r"((r)[21]),"=r"((r)[22]),"=r"((r)[23]), \
          "=r"((r)[24]),"=r"((r)[25]),"=r"((r)[26]),"=r"((r)[27]),"=r"((r)[28]),"=r"((r)[29]),"=r"((r)[30]),"=r"((r)[31]) \
        : "r"(addr))

constexpr uint32_t IDESC1 = (8u << 24) | ((Q   / 8u) << 17) | (1u << 10) | (1u << 7) | (1u << 4); // M=128,N=192
constexpr uint32_t IDESC2 = (8u << 24) | ((N2T / 8u) << 17) | (1u << 10) | (1u << 7) | (1u << 4); // M=128,N=256

__device__ __forceinline__ uint32_t pack_hi(float a, float b) {
    __nv_bfloat162 h = __floats2bfloat162_rn(a, b);
    return *reinterpret_cast<uint32_t*>(&h);
}
__device__ __forceinline__ uint32_t pack_lo(float a, float b, uint32_t hibits) {
    __nv_bfloat162 h = *reinterpret_cast<__nv_bfloat162*>(&hibits);
    __nv_bfloat162 l = __floats2bfloat162_rn(a - __bfloat162float(h.x),
                                             b - __bfloat162float(h.y));
    return *reinterpret_cast<uint32_t*>(&l);
}
#endif  // HAS_TCGEN05

// Barrier slots within HDR (relative to base):
//   +8  full[0]   +16 full[1]   (TMA B-tile completion, tx-based)
//   +24 mma[0]    +32 mma[1]    (MMA commit)

// ---------------------------------------------------------------------------
// Stage 1: grid (128, 4), 512 threads, dyn smem SMEM1
// ---------------------------------------------------------------------------
__global__ __launch_bounds__(NTHREADS) void stage1_kernel(const float* __restrict__ x,
                                                          const float* __restrict__ w1)
{
#if HAS_TCGEN05
    extern __shared__ char smem_raw[];
    const uint32_t raw = smem_u32(smem_raw);
    const uint32_t base = (raw + 1023u) & ~1023u;
    char* sm = smem_raw + (base - raw);

    const int t = threadIdx.x;
    const int wid = t >> 5, lid = t & 31;
    const int m0 = blockIdx.x * BM;
    const int kblk = blockIdx.y;

    if (wid == 0) TC_ALLOC(base, 512);
    if (t == 0) {
        MBAR_INIT(base + 8, 1);  MBAR_INIT(base + 16, 1);
        MBAR_INIT(base + 24, 1); MBAR_INIT(base + 32, 1);
    }
    __syncthreads();
    uint32_t tmem;
    asm volatile("ld.shared.b32 %0, [%1];" : "=r"(tmem) : "r"(base));

    const float* Ag = x + (size_t)m0 * IN_F + (size_t)kblk * P;

    // A-fill addressing: thread covers row = t>>2, cols [seg*16, seg*16+16)
    const int arow = t >> 2, aseg = t & 3;
    const uint32_t a_off0 = sw128((uint32_t)(arow * 128 + aseg * 32));
    const uint32_t a_off1 = sw128((uint32_t)(arow * 128 + aseg * 32 + 16));
    const float* a_src = Ag + (size_t)arow * IN_F + aseg * 16;

    int mph[2] = {0, 0};   // mma-done phases (all threads)
    int fph[2] = {0, 0};   // full (B-arrival) phases (used by elected; flipped by all)

    for (int c = 0; c < P / BK; ++c) {            // 16 chunks
        const int b = c & 1;
        if (c >= 2) { mbar_wait(base + 24 + b * 8, mph[b]); mph[b] ^= 1; }

        // B tile: async bulk copy of 48KB pre-swizzled image (elected thread)
        if (wid == 0 && elect_one()) {
            const char* srcB = (const char*)g_w1img + (size_t)(kblk * 16 + c) * S1_B_BYTES;
            MBAR_EXPECT_TX(base + 8 + b * 8, S1_B_BYTES);
            BULK_CP(base + HDR + b * S1_BUF + S1_B, srcB, S1_B_BYTES, base + 8 + b * 8);
        }

        // A tile: 4 float4 loads -> split -> 2+2 STS.128 (all threads)
        {
            char* Ahi = sm + HDR + b * S1_BUF;
            char* Alo = Ahi + S1_A_LO;
            const float4* s = reinterpret_cast<const float4*>(a_src + (size_t)c * BK);
            float4 a0 = s[0], a1 = s[1], a2 = s[2], a3 = s[3];
            uint4 h0, h1, l0, l1;
            h0.x = pack_hi(a0.x, a0.y); l0.x = pack_lo(a0.x, a0.y, h0.x);
            h0.y = pack_hi(a0.z, a0.w); l0.y = pack_lo(a0.z, a0.w, h0.y);
            h0.z = pack_hi(a1.x, a1.y); l0.z = pack_lo(a1.x, a1.y, h0.z);
            h0.w = pack_hi(a1.z, a1.w); l0.w = pack_lo(a1.z, a1.w, h0.w);
            h1.x = pack_hi(a2.x, a2.y); l1.x = pack_lo(a2.x, a2.y, h1.x);
            h1.y = pack_hi(a2.z, a2.w); l1.y = pack_lo(a2.z, a2.w, h1.y);
            h1.z = pack_hi(a3.x, a3.y); l1.z = pack_lo(a3.x, a3.y, h1.z);
            h1.w = pack_hi(a3.z, a3.w); l1.w = pack_lo(a3.z, a3.w, h1.w);
            *reinterpret_cast<uint4*>(Ahi + a_off0) = h0;
            *reinterpret_cast<uint4*>(Ahi + a_off1) = h1;
            *reinterpret_cast<uint4*>(Alo + a_off0) = l0;
            *reinterpret_cast<uint4*>(Alo + a_off1) = l1;
        }
        FENCE_ASYNC();
        __syncthreads();

        if (wid == 0 && elect_one()) {
            mbar_wait(base + 8 + b * 8, fph[b]);   // B arrived
            uint64_t dAh = make_desc(base + HDR + b * S1_BUF);
            uint64_t dAl = make_desc(base + HDR + b * S1_BUF + S1_A_LO);
            uint64_t dBh = make_desc(base + HDR + b * S1_BUF + S1_B);
            uint64_t dBl = make_desc(base + HDR + b * S1_BUF + S1_B + 24576);
            bool first = (c == 0);
#pragma unroll
            for (int ks = 0; ks < 4; ks++)
                mma_f16_ss(tmem, dAh + ks * 2, dBh + ks * 2, IDESC1, !(first && ks == 0));
#pragma unroll
            for (int ks = 0; ks < 4; ks++)
                mma_f16_ss(tmem, dAh + ks * 2, dBl + ks * 2, IDESC1, true);
#pragma unroll
            for (int ks = 0; ks < 4; ks++)
                mma_f16_ss(tmem, dAl + ks * 2, dBh + ks * 2, IDESC1, true);
            TC_COMMIT(base + 24 + b * 8);
        }
        fph[b] ^= 1;
    }

    mbar_wait(base + 24, mph[0]);
    mbar_wait(base + 32, mph[1]);
    TC_FENCE_AFTER();
    __syncthreads();

    float* stg = reinterpret_cast<float*>(sm + HDR);       // 128 x 193 f32
    if (wid < 4) {
        const int row = wid * 32 + lid;
#pragma unroll
        for (int cc = 0; cc < 6; ++cc) {
            uint32_t r32[32];
            TC_LD_X32(r32, tmem + cc * 32);
            TC_WAIT_LD();
#pragma unroll
            for (int j = 0; j < 32; ++j) stg[row * 193 + cc * 32 + j] = __uint_as_float(r32[j]);
        }
    }
    __syncthreads();

    for (int u = t; u < 128 * 192; u += NTHREADS) {
        int r = u / 192, q = u - r * 192;
        int l = q / B1C, b1 = q - l * B1C;
        float f = stg[r * 193 + q];
        __nv_bfloat16 h = __float2bfloat16_rn(f);
        __nv_bfloat16 lo = __float2bfloat16_rn(f - __bfloat162float(h));
        uint32_t packed = (uint32_t)__bfloat16_as_ushort(h) |
                          ((uint32_t)__bfloat16_as_ushort(lo) << 16);
        g_mid[(size_t)(m0 + r) * MIDW + l * R + kblk * B1C + b1] = packed;
    }

    __syncthreads();
    if (wid == 0) { TC_RELINQ(); TC_DEALLOC(tmem, 512); }
#else
    // ---- fp32 SIMT fallback: CTA 128 x 192, K=1024, 512 threads ----
    extern __shared__ char smem_raw[];
    float* As = reinterpret_cast<float*>(smem_raw);          // [16][132]
    float* Bs = As + 16 * 132;                               // [16][196]

    const int t = threadIdx.x;
    const int ty = t >> 5;
    const int tx = t & 31;
    const int m0 = blockIdx.x * BM;
    const int kblk = blockIdx.y;

    const float* Ag = x  + (size_t)m0 * IN_F + (size_t)kblk * P;
    const float* Bg = w1 + (size_t)kblk * Q * P;

    float c[8][6];
#pragma unroll
    for (int i = 0; i < 8; i++)
#pragma unroll
        for (int j = 0; j < 6; j++) c[i][j] = 0.f;

    for (int k0 = 0; k0 < P; k0 += 16) {
        {
            int u = t;
            int m = u >> 2, kq = (u & 3) << 2;
            float4 v = *reinterpret_cast<const float4*>(Ag + (size_t)m * IN_F + k0 + kq);
            As[(kq + 0) * 132 + m] = v.x; As[(kq + 1) * 132 + m] = v.y;
            As[(kq + 2) * 132 + m] = v.z; As[(kq + 3) * 132 + m] = v.w;
        }
        for (int u = t; u < 768; u += NTHREADS) {
            int q = u >> 2, kq = (u & 3) << 2;
            float4 v = *reinterpret_cast<const float4*>(Bg + (size_t)q * P + k0 + kq);
            Bs[(kq + 0) * 196 + q] = v.x; Bs[(kq + 1) * 196 + q] = v.y;
            Bs[(kq + 2) * 196 + q] = v.z; Bs[(kq + 3) * 196 + q] = v.w;
        }
        __syncthreads();

#pragma unroll
        for (int kk = 0; kk < 16; kk++) {
            float a[8], bb[6];
#pragma unroll
            for (int i = 0; i < 8; i++) a[i] = As[kk * 132 + ty * 8 + i];
#pragma unroll
            for (int j = 0; j < 6; j++) bb[j] = Bs[kk * 196 + tx * 6 + j];
#pragma unroll
            for (int i = 0; i < 8; i++)
#pragma unroll
                for (int j = 0; j < 6; j++)
                    c[i][j] = fmaf(a[i], bb[j], c[i][j]);
        }
        __syncthreads();
    }

#pragma unroll
    for (int i = 0; i < 8; i++) {
        int m = m0 + ty * 8 + i;
#pragma unroll
        for (int j = 0; j < 6; j++) {
            int q = tx * 6 + j;
            int l = q / B1C, b1 = q - l * B1C;
            g_mid[(size_t)m * MIDW + l * R + kblk * B1C + b1] = __float_as_uint(c[i][j]);
        }
    }
#endif
}

// ---------------------------------------------------------------------------
// Stage 2: grid (128, 4, 4), 512 threads, dyn smem SMEM2
// ---------------------------------------------------------------------------
__global__ __launch_bounds__(NTHREADS) void stage2_kernel(const float* __restrict__ w2,
                                                          const float* __restrict__ bias,
                                                          float* __restrict__ out)
{
#if HAS_TCGEN05
    extern __shared__ char smem_raw[];
    const uint32_t raw = smem_u32(smem_raw);
    const uint32_t base = (raw + 1023u) & ~1023u;
    char* sm = smem_raw + (base - raw);

    const int t = threadIdx.x;
    const int wid = t >> 5, lid = t & 31;
    const int m0 = blockIdx.x * BM;
    const int n0 = blockIdx.y * N2T;
    const int lblk = blockIdx.z;

    if (wid == 0) TC_ALLOC(base, 512);
    if (t == 0) {
        MBAR_INIT(base + 8, 1);  MBAR_INIT(base + 16, 1);
        MBAR_INIT(base + 24, 1); MBAR_INIT(base + 32, 1);
    }
    __syncthreads();
    uint32_t tmem;
    asm volatile("ld.shared.b32 %0, [%1];" : "=r"(tmem) : "r"(base));

    const uint32_t* Ag = g_mid + (size_t)m0 * MIDW + lblk * R;

    const int arow = t >> 2, aseg = t & 3;       // cols [aseg*16, +16)
    const uint32_t a_off0 = sw128((uint32_t)(arow * 128 + aseg * 32));
    const uint32_t a_off1 = sw128((uint32_t)(arow * 128 + aseg * 32 + 16));
    const uint32_t* a_src = Ag + (size_t)arow * MIDW + aseg * 16;

    int mph[2] = {0, 0};
    int fph[2] = {0, 0};

    for (int c = 0; c < R / BK; ++c) {            // 3 chunks
        const int b = c & 1;
        if (c >= 2) { mbar_wait(base + 24 + b * 8, mph[b]); mph[b] ^= 1; }

        // B tile: async bulk copy of 64KB pre-swizzled image (elected thread)
        if (wid == 0 && elect_one()) {
            const char* srcB = (const char*)g_w2img +
                               (size_t)(((lblk * 4 + (n0 >> 8)) * 3) + c) * S2_B_BYTES;
            MBAR_EXPECT_TX(base + 8 + b * 8, S2_B_BYTES);
            BULK_CP(base + HDR + b * S2_BUF + S2_B, srcB, S2_B_BYTES, base + 8 + b * 8);
        }

        // A tile: 4 uint4 packed loads -> PRMT split -> 2+2 STS.128
        {
            char* Ahi = sm + HDR + b * S2_BUF;
            char* Alo = Ahi + S2_A_LO;
            const uint4* s = reinterpret_cast<const uint4*>(a_src + (size_t)c * BK);
            uint4 p0 = s[0], p1 = s[1], p2 = s[2], p3 = s[3];
            uint4 h0, h1, l0, l1;
            h0.x = __byte_perm(p0.x, p0.y, 0x5410); l0.x = __byte_perm(p0.x, p0.y, 0x7632);
            h0.y = __byte_perm(p0.z, p0.w, 0x5410); l0.y = __byte_perm(p0.z, p0.w, 0x7632);
            h0.z = __byte_perm(p1.x, p1.y, 0x5410); l0.z = __byte_perm(p1.x, p1.y, 0x7632);
            h0.w = __byte_perm(p1.z, p1.w, 0x5410); l0.w = __byte_perm(p1.z, p1.w, 0x7632);
            h1.x = __byte_perm(p2.x, p2.y, 0x5410); l1.x = __byte_perm(p2.x, p2.y, 0x7632);
            h1.y = __byte_perm(p2.z, p2.w, 0x5410); l1.y = __byte_perm(p2.z, p2.w, 0x7632);
            h1.z = __byte_perm(p3.x, p3.y, 0x5410); l1.z = __byte_perm(p3.x, p3.y, 0x7632);
            h1.w = __byte_perm(p3.z, p3.w, 0x5410); l1.w = __byte_perm(p3.z, p3.w, 0x7632);
            *reinterpret_cast<uint4*>(Ahi + a_off0) = h0;
            *reinterpret_cast<uint4*>(Ahi + a_off1) = h1;
            *reinterpret_cast<uint4*>(Alo + a_off0) = l0;
            *reinterpret_cast<uint4*>(Alo + a_off1) = l1;
        }
        FENCE_ASYNC();
        __syncthreads();

        if (wid == 0 && elect_one()) {
            mbar_wait(base + 8 + b * 8, fph[b]);   // B arrived
            uint64_t dAh = make_desc(base + HDR + b * S2_BUF);
            uint64_t dAl = make_desc(base + HDR + b * S2_BUF + S2_A_LO);
            uint64_t dBh = make_desc(base + HDR + b * S2_BUF + S2_B);
            uint64_t dBl = make_desc(base + HDR + b * S2_BUF + S2_B + 32768);
            bool first = (c == 0);
#pragma unroll
            for (int ks = 0; ks < 4; ks++)
                mma_f16_ss(tmem, dAh + ks * 2, dBh + ks * 2, IDESC2, !(first && ks == 0));
#pragma unroll
            for (int ks = 0; ks < 4; ks++)
                mma_f16_ss(tmem, dAh + ks * 2, dBl + ks * 2, IDESC2, true);
#pragma unroll
            for (int ks = 0; ks < 4; ks++)
                mma_f16_ss(tmem, dAl + ks * 2, dBh + ks * 2, IDESC2, true);
            TC_COMMIT(base + 24 + b * 8);
        }
        fph[b] ^= 1;
    }

    mbar_wait(base + 24, mph[0]);
    mbar_wait(base + 32, mph[1]);
    TC_FENCE_AFTER();
    __syncthreads();

    float* stg = reinterpret_cast<float*>(sm + HDR);       // 128 x 257 f32
    if (wid < 4) {
        const int row = wid * 32 + lid;
#pragma unroll
        for (int cc = 0; cc < 8; ++cc) {
            uint32_t r32[32];
            TC_LD_X32(r32, tmem + cc * 32);
            TC_WAIT_LD();
#pragma unroll
            for (int j = 0; j < 32; ++j) stg[row * 257 + cc * 32 + j] = __uint_as_float(r32[j]);
        }
    }
    __syncthreads();

    const int col = t & 255;
    const int rhalf = t >> 8;                    // 0 or 1
    const float bv = bias[lblk * S + n0 + col];
    float* og = out + (size_t)m0 * OUT_F + lblk * S + n0 + col;
#pragma unroll 4
    for (int rr = 0; rr < 64; ++rr) {
        int row = rhalf * 64 + rr;
        og[(size_t)row * OUT_F] = stg[row * 257 + col] + bv;
    }

    __syncthreads();
    if (wid == 0) { TC_RELINQ(); TC_DEALLOC(tmem, 512); }
#else
    // ---- fp32 SIMT fallback: CTA 128 x 256, K=192, 512 threads ----
    extern __shared__ char smem_raw[];
    float* As = reinterpret_cast<float*>(smem_raw);          // [16][132]
    float* Bs = As + 16 * 132;                               // [16][260]

    const int t = threadIdx.x;
    const int ty = t >> 5;
    const int tx = t & 31;
    const int m0 = blockIdx.x * BM;
    const int n0 = blockIdx.y * N2T;
    const int lblk = blockIdx.z;

    const float* Af = reinterpret_cast<const float*>(g_mid) + (size_t)m0 * MIDW + lblk * R;
    const float* Bg = w2 + (size_t)lblk * S * R + (size_t)n0 * R;

    float c[8][8];
#pragma unroll
    for (int i = 0; i < 8; i++)
#pragma unroll
        for (int j = 0; j < 8; j++) c[i][j] = 0.f;

    for (int k0 = 0; k0 < R; k0 += 16) {
        {
            int u = t;
            int m = u >> 2, kq = (u & 3) << 2;
            float4 v = *reinterpret_cast<const float4*>(Af + (size_t)m * MIDW + k0 + kq);
            As[(kq + 0) * 132 + m] = v.x; As[(kq + 1) * 132 + m] = v.y;
            As[(kq + 2) * 132 + m] = v.z; As[(kq + 3) * 132 + m] = v.w;
        }
        for (int u = t; u < 1024; u += NTHREADS) {
            int q = u >> 2, kq = (u & 3) << 2;
            float4 v = *reinterpret_cast<const float4*>(Bg + (size_t)q * R + k0 + kq);
            Bs[(kq + 0) * 260 + q] = v.x; Bs[(kq + 1) * 260 + q] = v.y;
            Bs[(kq + 2) * 260 + q] = v.z; Bs[(kq + 3) * 260 + q] = v.w;
        }
        __syncthreads();

#pragma unroll
        for (int kk = 0; kk < 16; kk++) {
            float a[8], bb[8];
#pragma unroll
            for (int i = 0; i < 8; i++) a[i] = As[kk * 132 + ty * 8 + i];
#pragma unroll
            for (int j = 0; j < 8; j++) bb[j] = Bs[kk * 260 + tx * 8 + j];
#pragma unroll
            for (int i = 0; i < 8; i++)
#pragma unroll
                for (int j = 0; j < 8; j++)
                    c[i][j] = fmaf(a[i], bb[j], c[i][j]);
        }
        __syncthreads();
    }

#pragma unroll
    for (int j = 0; j < 8; j++) {
        int sg = n0 + tx * 8 + j;
        float bv = bias[lblk * S + sg];
#pragma unroll
        for (int i = 0; i < 8; i++) {
            int m = m0 + ty * 8 + i;
            out[(size_t)m * OUT_F + lblk * S + sg] = c[i][j] + bv;
        }
    }
#endif
}

// ---------------------------------------------------------------------------
extern "C" void kernel_launch(void* const* d_in, const int* in_sizes, int n_in,
                              void* d_out, int out_size)
{
    const float* x    = (const float*)d_in[0];
    const float* w1   = (const float*)d_in[1];
    const float* w2   = (const float*)d_in[2];
    const float* bias = (const float*)d_in[3];
    float* out = (float*)d_out;

    // Unconditional (no static guards): identical work on every call.
    cudaFuncSetAttribute(stage1_kernel, cudaFuncAttributeMaxDynamicSharedMemorySize, SMEM1);
    cudaFuncSetAttribute(stage2_kernel, cudaFuncAttributeMaxDynamicSharedMemorySize, SMEM2);

    conv_w1_kernel<<<1536, 256>>>(w1);
    conv_w2_kernel<<<1536, 256>>>(w2);

    dim3 g1(BATCH / BM, NB1, 1);          // (128, 4)
    stage1_kernel<<<g1, NTHREADS, SMEM1>>>(x, w1);

    dim3 g2(BATCH / BM, S / N2T, NB2);    // (128, 4, 4)
    stage2_kernel<<<g2, NTHREADS, SMEM2>>>(w2, bias, out);
}

// round 12
// speedup vs baseline: 5.8523x; 1.2582x over previous
#include <cuda_runtime.h>
#include <cuda_bf16.h>
#include <cstdint>

// Monarch butterfly linear, tcgen05 bf16 split-precision (hi/lo) GEMMs.
// Single-buffered smem pipeline at 2 CTAs/SM: cross-CTA overlap hides fill
// latency, prologue, and epilogue. B tiles stream via cp.async.bulk from
// pre-swizzled weight images. Plain compute_103 passes get fp32 SIMT fallback.

#if defined(__CUDA_ARCH__) && (defined(__CUDA_ARCH_FEAT_SM103_ALL) || defined(__CUDA_ARCH_FEAT_SM100_ALL))
#define HAS_TCGEN05 1
#else
#define HAS_TCGEN05 0
#endif

constexpr int BATCH = 16384;
constexpr int IN_F  = 4096;
constexpr int OUT_F = 4096;
constexpr int NB1 = 4, NB2 = 4, B1C = 48;
constexpr int P = 1024;   // stage1 K
constexpr int Q = 192;    // stage1 N
constexpr int R = 192;    // stage2 K
constexpr int S = 1024;   // stage2 N per l-block
constexpr int MIDW = NB2 * R;  // 768

constexpr int BM = 128;
constexpr int BK = 64;    // 64 bf16 cols = 128B = one SW128 atom row
constexpr int N2T = 256;  // stage2 N tile
constexpr int NTHREADS = 512;

// Scratch: intermediate packed (bf16 hi | bf16 lo) [48 MB] (fallback: fp32 bits)
__device__ uint32_t g_mid[(size_t)BATCH * MIDW];
// Pre-swizzled weight images (bf16 hi plane | lo plane per chunk), 3 MB each.
// w1: [kblk][chunk16][hi 24K | lo 24K]   w2: [lblk][ntile4][chunk3][hi 32K | lo 32K]
__device__ uint4 g_w1img[4 * 16 * 49152 / 16];
__device__ uint4 g_w2img[4 * 4 * 3 * 65536 / 16];

constexpr int HDR = 1024;
// stage1 buffer (single): Ahi 16K | Alo 16K | B(hi+lo) 48K = 80K
constexpr int S1_A_LO = 16384, S1_B = 32768, S1_BUF = 81920;
constexpr int S1_B_BYTES = 49152;
constexpr int SMEM1 = 1024 + HDR + S1_BUF;              // 83968  -> 2 CTAs/SM
// stage2 buffer (single): Ahi 16K | Alo 16K | B(hi+lo) 64K = 96K
constexpr int S2_A_LO = 16384, S2_B = 32768, S2_BUF = 98304;
constexpr int S2_B_BYTES = 65536;
constexpr int SMEM2 = 1024 + HDR + S2_BUF;              // 100352 -> 2 CTAs/SM

__host__ __device__ __forceinline__ uint32_t sw128(uint32_t byte_off) {
    return byte_off ^ ((byte_off >> 3) & 0x70);
}

// ---------------------------------------------------------------------------
// Weight pre-conversion kernels (plain CUDA, both compile variants)
// ---------------------------------------------------------------------------
__global__ __launch_bounds__(256) void conv_w1_kernel(const float* __restrict__ w1)
{
    int id = blockIdx.x * 256 + threadIdx.x;          // [0, 4*192*512)
    if (id >= 4 * 192 * 512) return;
    int k   = id / (192 * 512);
    int rem = id % (192 * 512);
    int row = rem / 512;
    int col = (rem % 512) * 2;
    float2 v = *reinterpret_cast<const float2*>(w1 + ((size_t)k * Q + row) * P + col);
    __nv_bfloat162 h = __floats2bfloat162_rn(v.x, v.y);
    __nv_bfloat162 l = __floats2bfloat162_rn(v.x - __bfloat162float(h.x),
                                             v.y - __bfloat162float(h.y));
    int chunk = col >> 6, cw = col & 63;
    char* img = (char*)g_w1img + (size_t)(k * 16 + chunk) * 49152;
    uint32_t off = sw128((uint32_t)(row * 128 + cw * 2));
    *reinterpret_cast<uint32_t*>(img + off)         = *reinterpret_cast<uint32_t*>(&h);
    *reinterpret_cast<uint32_t*>(img + 24576 + off) = *reinterpret_cast<uint32_t*>(&l);
}

__global__ __launch_bounds__(256) void conv_w2_kernel(const float* __restrict__ w2)
{
    int id = blockIdx.x * 256 + threadIdx.x;          // [0, 4*1024*96)
    if (id >= 4 * 1024 * 96) return;
    int l   = id / (1024 * 96);
    int rem = id % (1024 * 96);
    int s   = rem / 96;
    int col = (rem % 96) * 2;
    float2 v = *reinterpret_cast<const float2*>(w2 + ((size_t)l * S + s) * R + col);
    __nv_bfloat162 h = __floats2bfloat162_rn(v.x, v.y);
    __nv_bfloat162 lo = __floats2bfloat162_rn(v.x - __bfloat162float(h.x),
                                              v.y - __bfloat162float(h.y));
    int chunk = col >> 6, cw = col & 63;
    int ntile = s >> 8, rt = s & 255;
    char* img = (char*)g_w2img + (size_t)(((l * 4 + ntile) * 3) + chunk) * 65536;
    uint32_t off = sw128((uint32_t)(rt * 128 + cw * 2));
    *reinterpret_cast<uint32_t*>(img + off)         = *reinterpret_cast<uint32_t*>(&h);
    *reinterpret_cast<uint32_t*>(img + 32768 + off) = *reinterpret_cast<uint32_t*>(&lo);
}

#if HAS_TCGEN05
// ---------------------------------------------------------------------------
// PTX helpers (arch-specific pass only)
// ---------------------------------------------------------------------------
__device__ __forceinline__ uint32_t smem_u32(const void* p) {
    uint32_t a;
    asm("{ .reg .u64 t; cvta.to.shared.u64 t, %1; cvt.u32.u64 %0, t; }" : "=r"(a) : "l"(p));
    return a;
}
__device__ __forceinline__ bool elect_one() {
    uint32_t pred;
    asm volatile("{ .reg .pred p; elect.sync _|p, 0xFFFFFFFF; selp.b32 %0, 1, 0, p; }" : "=r"(pred));
    return pred != 0;
}
static constexpr uint64_t DESC_BASE_SW128 =
    (uint64_t(2)  << 61) | (uint64_t(1) << 46) | (uint64_t(64) << 32) | (uint64_t(1) << 16);
__device__ __forceinline__ uint64_t make_desc(uint32_t smem_addr) {
    return DESC_BASE_SW128 | ((uint64_t)(smem_addr >> 4) & 0x3FFF);
}

#define TC_ALLOC(smem_ptr_addr, n) \
    asm volatile("tcgen05.alloc.cta_group::1.sync.aligned.shared::cta.b32 [%0], %1;" \
                 :: "r"(smem_ptr_addr), "r"((uint32_t)(n)) : "memory")
#define TC_DEALLOC(tmem, n) \
    asm volatile("tcgen05.dealloc.cta_group::1.sync.aligned.b32 %0, %1;" :: "r"(tmem), "r"((uint32_t)(n)))
#define TC_RELINQ() \
    asm volatile("tcgen05.relinquish_alloc_permit.cta_group::1.sync.aligned;")
#define TC_COMMIT(mbar) \
    asm volatile("tcgen05.commit.cta_group::1.mbarrier::arrive::one.shared::cluster.b64 [%0];" \
                 :: "r"(mbar) : "memory")
#define TC_FENCE_AFTER()  asm volatile("tcgen05.fence::after_thread_sync;" ::: "memory")
#define TC_WAIT_LD()      asm volatile("tcgen05.wait::ld.sync.aligned;" ::: "memory")
#define FENCE_ASYNC()     asm volatile("fence.proxy.async.shared::cta;" ::: "memory")
#define MBAR_INIT(mbar, n) \
    asm volatile("mbarrier.init.shared.b64 [%0], %1;" :: "r"(mbar), "r"((uint32_t)(n)) : "memory")
#define MBAR_EXPECT_TX(mbar, bytes) \
    asm volatile("mbarrier.arrive.expect_tx.shared.b64 _, [%0], %1;" \
                 :: "r"(mbar), "r"((uint32_t)(bytes)) : "memory")
#define BULK_CP(dst_smem, src_gmem, bytes, mbar) \
    asm volatile("cp.async.bulk.shared::cta.global.mbarrier::complete_tx::bytes [%0], [%1], %2, [%3];" \
                 :: "r"(dst_smem), "l"(src_gmem), "r"((uint32_t)(bytes)), "r"(mbar) : "memory")

__device__ __forceinline__ void mbar_wait(uint32_t mbar, int parity) {
    uint32_t done;
    asm volatile("{ .reg .pred p; mbarrier.try_wait.parity.acquire.cta.shared::cta.b64 p, [%1], %2; selp.b32 %0, 1, 0, p; }"
                 : "=r"(done) : "r"(mbar), "r"((uint32_t)parity) : "memory");
    if (!done) {
        asm volatile(
            "{ .reg .pred P1;\n"
            "WAIT_%=: mbarrier.try_wait.parity.acquire.cta.shared::cta.b64 P1, [%0], %1, 0x989680;\n"
            "@P1 bra.uni DONE_%=;\n"
            "bra.uni WAIT_%=;\n"
            "DONE_%=: }"
            :: "r"(mbar), "r"((uint32_t)parity) : "memory");
    }
}

__device__ __forceinline__ void mma_f16_ss(uint32_t d_tmem, uint64_t a_desc, uint64_t b_desc,
                                           uint32_t idesc, bool acc) {
    uint32_t en = acc ? 1u : 0u;
    asm volatile(
        "{ .reg .pred p; setp.ne.u32 p, %4, 0;\n"
        "tcgen05.mma.cta_group::1.kind::f16 [%0], %1, %2, %3, {%5, %5, %5, %5}, p; }"
        :: "r"(d_tmem), "l"(a_desc), "l"(b_desc), "r"(idesc), "r"(en), "r"(0u)
        : "memory");
}

#define TC_LD_X32(r, addr) \
    asm volatile("tcgen05.ld.sync.aligned.32x32b.x32.b32 " \
        "{%0,%1,%2,%3,%4,%5,%6,%7,%8,%9,%10,%11,%12,%13,%14,%15," \
        "%16,%17,%18,%19,%20,%21,%22,%23,%24,%25,%26,%27,%28,%29,%30,%31}, [%32];" \
        : "=r"((r)[0]),"=r"((r)[1]),"=r"((r)[2]),"=r"((r)[3]),"=r"((r)[4]),"=r"((r)[5]),"=r"((r)[6]),"=r"((r)[7]), \
          "=r"((r)[8]),"=r"((r)[9]),"=r"((r)[10]),"=r"((r)[11]),"=r"((r)[12]),"=r"((r)[13]),"=r"((r)[14]),"=r"((r)[15]), \
          "=r"((r)[16]),"=r"((r)[17]),"=r"((r)[18]),"=r"((r)[19]),"=r"((r)[20]),"=r"((r)[21]),"=r"((r)[22]),"=r"((r)[23]), \
          "=r"((r)[24]),"=r"((r)[25]),"=r"((r)[26]),"=r"((r)[27]),"=r"((r)[28]),"=r"((r)[29]),"=r"((r)[30]),"=r"((r)[31]) \
        : "r"(addr))

constexpr uint32_t IDESC1 = (8u << 24) | ((Q   / 8u) << 17) | (1u << 10) | (1u << 7) | (1u << 4); // M=128,N=192
constexpr uint32_t IDESC2 = (8u << 24) | ((N2T / 8u) << 17) | (1u << 10) | (1u << 7) | (1u << 4); // M=128,N=256

__device__ __forceinline__ uint32_t pack_hi(float a, float b) {
    __nv_bfloat162 h = __floats2bfloat162_rn(a, b);
    return *reinterpret_cast<uint32_t*>(&h);
}
__device__ __forceinline__ uint32_t pack_lo(float a, float b, uint32_t hibits) {
    __nv_bfloat162 h = *reinterpret_cast<__nv_bfloat162*>(&hibits);
    __nv_bfloat162 l = __floats2bfloat162_rn(a - __bfloat162float(h.x),
                                             b - __bfloat162float(h.y));
    return *reinterpret_cast<uint32_t*>(&l);
}
#endif  // HAS_TCGEN05

// Barrier slots within HDR (relative to base):
//   +8  full   (bulk-cp B-tile completion, tx-based)
//   +24 mma    (MMA commit)

// ---------------------------------------------------------------------------
// Stage 1: grid (128, 4), 512 threads, dyn smem SMEM1, 2 CTAs/SM
// ---------------------------------------------------------------------------
__global__ __launch_bounds__(NTHREADS, 2) void stage1_kernel(const float* __restrict__ x,
                                                             const float* __restrict__ w1)
{
#if HAS_TCGEN05
    extern __shared__ char smem_raw[];
    const uint32_t raw = smem_u32(smem_raw);
    const uint32_t base = (raw + 1023u) & ~1023u;
    char* sm = smem_raw + (base - raw);

    const int t = threadIdx.x;
    const int wid = t >> 5, lid = t & 31;
    const int m0 = blockIdx.x * BM;
    const int kblk = blockIdx.y;

    if (wid == 0) { TC_ALLOC(base, 256); TC_RELINQ(); }
    if (t == 0) { MBAR_INIT(base + 8, 1); MBAR_INIT(base + 24, 1); }
    __syncthreads();
    uint32_t tmem;
    asm volatile("ld.shared.b32 %0, [%1];" : "=r"(tmem) : "r"(base));

    const float* Ag = x + (size_t)m0 * IN_F + (size_t)kblk * P;

    // A-fill addressing: thread covers row = t>>2, cols [seg*16, seg*16+16)
    const int arow = t >> 2, aseg = t & 3;
    const uint32_t a_off0 = sw128((uint32_t)(arow * 128 + aseg * 32));
    const uint32_t a_off1 = sw128((uint32_t)(arow * 128 + aseg * 32 + 16));
    const float* a_src = Ag + (size_t)arow * IN_F + aseg * 16;

    char* Ahi = sm + HDR;
    char* Alo = Ahi + S1_A_LO;
    const uint64_t dAh = make_desc(base + HDR);
    const uint64_t dAl = make_desc(base + HDR + S1_A_LO);
    const uint64_t dBh = make_desc(base + HDR + S1_B);
    const uint64_t dBl = make_desc(base + HDR + S1_B + 24576);

    int mph = 0, fph = 0;

    for (int c = 0; c < P / BK; ++c) {            // 16 chunks
        if (c >= 1) { mbar_wait(base + 24, mph); mph ^= 1; }

        if (wid == 0 && elect_one()) {
            const char* srcB = (const char*)g_w1img + (size_t)(kblk * 16 + c) * S1_B_BYTES;
            MBAR_EXPECT_TX(base + 8, S1_B_BYTES);
            BULK_CP(base + HDR + S1_B, srcB, S1_B_BYTES, base + 8);
        }

        // A tile: 4 float4 loads -> split -> 2+2 STS.128 (all threads)
        {
            const float4* s = reinterpret_cast<const float4*>(a_src + (size_t)c * BK);
            float4 a0 = s[0], a1 = s[1], a2 = s[2], a3 = s[3];
            uint4 h0, h1, l0, l1;
            h0.x = pack_hi(a0.x, a0.y); l0.x = pack_lo(a0.x, a0.y, h0.x);
            h0.y = pack_hi(a0.z, a0.w); l0.y = pack_lo(a0.z, a0.w, h0.y);
            h0.z = pack_hi(a1.x, a1.y); l0.z = pack_lo(a1.x, a1.y, h0.z);
            h0.w = pack_hi(a1.z, a1.w); l0.w = pack_lo(a1.z, a1.w, h0.w);
            h1.x = pack_hi(a2.x, a2.y); l1.x = pack_lo(a2.x, a2.y, h1.x);
            h1.y = pack_hi(a2.z, a2.w); l1.y = pack_lo(a2.z, a2.w, h1.y);
            h1.z = pack_hi(a3.x, a3.y); l1.z = pack_lo(a3.x, a3.y, h1.z);
            h1.w = pack_hi(a3.z, a3.w); l1.w = pack_lo(a3.z, a3.w, h1.w);
            *reinterpret_cast<uint4*>(Ahi + a_off0) = h0;
            *reinterpret_cast<uint4*>(Ahi + a_off1) = h1;
            *reinterpret_cast<uint4*>(Alo + a_off0) = l0;
            *reinterpret_cast<uint4*>(Alo + a_off1) = l1;
        }
        FENCE_ASYNC();
        __syncthreads();

        if (wid == 0 && elect_one()) {
            mbar_wait(base + 8, fph);   // B arrived
            bool first = (c == 0);
#pragma unroll
            for (int ks = 0; ks < 4; ks++)
                mma_f16_ss(tmem, dAh + ks * 2, dBh + ks * 2, IDESC1, !(first && ks == 0));
#pragma unroll
            for (int ks = 0; ks < 4; ks++)
                mma_f16_ss(tmem, dAh + ks * 2, dBl + ks * 2, IDESC1, true);
#pragma unroll
            for (int ks = 0; ks < 4; ks++)
                mma_f16_ss(tmem, dAl + ks * 2, dBh + ks * 2, IDESC1, true);
            TC_COMMIT(base + 24);
        }
        fph ^= 1;
    }

    mbar_wait(base + 24, mph);
    TC_FENCE_AFTER();
    __syncthreads();

    // Epilogue in 3 passes of 64 cols (staging 128x65 f32 = 33.3KB <= buffer)
    float* stg = reinterpret_cast<float*>(sm + HDR);
    for (int cc3 = 0; cc3 < 3; ++cc3) {
        if (wid < 4) {
            const int row = wid * 32 + lid;
            uint32_t r32[32];
            TC_LD_X32(r32, tmem + cc3 * 64);
            TC_WAIT_LD();
#pragma unroll
            for (int j = 0; j < 32; ++j) stg[row * 65 + j] = __uint_as_float(r32[j]);
            TC_LD_X32(r32, tmem + cc3 * 64 + 32);
            TC_WAIT_LD();
#pragma unroll
            for (int j = 0; j < 32; ++j) stg[row * 65 + 32 + j] = __uint_as_float(r32[j]);
        }
        __syncthreads();

        for (int u = t; u < 128 * 64; u += NTHREADS) {
            int r = u >> 6, q = (u & 63) + cc3 * 64;
            int l = q / B1C, b1 = q - l * B1C;
            float f = stg[r * 65 + (u & 63)];
            __nv_bfloat16 h = __float2bfloat16_rn(f);
            __nv_bfloat16 lo = __float2bfloat16_rn(f - __bfloat162float(h));
            uint32_t packed = (uint32_t)__bfloat16_as_ushort(h) |
                              ((uint32_t)__bfloat16_as_ushort(lo) << 16);
            g_mid[(size_t)(m0 + r) * MIDW + l * R + kblk * B1C + b1] = packed;
        }
        __syncthreads();
    }

    if (wid == 0) TC_DEALLOC(tmem, 256);
#else
    // ---- fp32 SIMT fallback: CTA 128 x 192, K=1024, 512 threads ----
    extern __shared__ char smem_raw[];
    float* As = reinterpret_cast<float*>(smem_raw);          // [16][132]
    float* Bs = As + 16 * 132;                               // [16][196]

    const int t = threadIdx.x;
    const int ty = t >> 5;
    const int tx = t & 31;
    const int m0 = blockIdx.x * BM;
    const int kblk = blockIdx.y;

    const float* Ag = x  + (size_t)m0 * IN_F + (size_t)kblk * P;
    const float* Bg = w1 + (size_t)kblk * Q * P;

    float c[8][6];
#pragma unroll
    for (int i = 0; i < 8; i++)
#pragma unroll
        for (int j = 0; j < 6; j++) c[i][j] = 0.f;

    for (int k0 = 0; k0 < P; k0 += 16) {
        {
            int u = t;
            int m = u >> 2, kq = (u & 3) << 2;
            float4 v = *reinterpret_cast<const float4*>(Ag + (size_t)m * IN_F + k0 + kq);
            As[(kq + 0) * 132 + m] = v.x; As[(kq + 1) * 132 + m] = v.y;
            As[(kq + 2) * 132 + m] = v.z; As[(kq + 3) * 132 + m] = v.w;
        }
        for (int u = t; u < 768; u += NTHREADS) {
            int q = u >> 2, kq = (u & 3) << 2;
            float4 v = *reinterpret_cast<const float4*>(Bg + (size_t)q * P + k0 + kq);
            Bs[(kq + 0) * 196 + q] = v.x; Bs[(kq + 1) * 196 + q] = v.y;
            Bs[(kq + 2) * 196 + q] = v.z; Bs[(kq + 3) * 196 + q] = v.w;
        }
        __syncthreads();

#pragma unroll
        for (int kk = 0; kk < 16; kk++) {
            float a[8], bb[6];
#pragma unroll
            for (int i = 0; i < 8; i++) a[i] = As[kk * 132 + ty * 8 + i];
#pragma unroll
            for (int j = 0; j < 6; j++) bb[j] = Bs[kk * 196 + tx * 6 + j];
#pragma unroll
            for (int i = 0; i < 8; i++)
#pragma unroll
                for (int j = 0; j < 6; j++)
                    c[i][j] = fmaf(a[i], bb[j], c[i][j]);
        }
        __syncthreads();
    }

#pragma unroll
    for (int i = 0; i < 8; i++) {
        int m = m0 + ty * 8 + i;
#pragma unroll
        for (int j = 0; j < 6; j++) {
            int q = tx * 6 + j;
            int l = q / B1C, b1 = q - l * B1C;
            g_mid[(size_t)m * MIDW + l * R + kblk * B1C + b1] = __float_as_uint(c[i][j]);
        }
    }
#endif
}

// ---------------------------------------------------------------------------
// Stage 2: grid (128, 4, 4), 512 threads, dyn smem SMEM2, 2 CTAs/SM
// ---------------------------------------------------------------------------
__global__ __launch_bounds__(NTHREADS, 2) void stage2_kernel(const float* __restrict__ w2,
                                                             const float* __restrict__ bias,
                                                             float* __restrict__ out)
{
#if HAS_TCGEN05
    extern __shared__ char smem_raw[];
    const uint32_t raw = smem_u32(smem_raw);
    const uint32_t base = (raw + 1023u) & ~1023u;
    char* sm = smem_raw + (base - raw);

    const int t = threadIdx.x;
    const int wid = t >> 5, lid = t & 31;
    const int m0 = blockIdx.x * BM;
    const int n0 = blockIdx.y * N2T;
    const int lblk = blockIdx.z;

    if (wid == 0) { TC_ALLOC(base, 256); TC_RELINQ(); }
    if (t == 0) { MBAR_INIT(base + 8, 1); MBAR_INIT(base + 24, 1); }
    __syncthreads();
    uint32_t tmem;
    asm volatile("ld.shared.b32 %0, [%1];" : "=r"(tmem) : "r"(base));

    const uint32_t* Ag = g_mid + (size_t)m0 * MIDW + lblk * R;

    const int arow = t >> 2, aseg = t & 3;       // cols [aseg*16, +16)
    const uint32_t a_off0 = sw128((uint32_t)(arow * 128 + aseg * 32));
    const uint32_t a_off1 = sw128((uint32_t)(arow * 128 + aseg * 32 + 16));
    const uint32_t* a_src = Ag + (size_t)arow * MIDW + aseg * 16;

    char* Ahi = sm + HDR;
    char* Alo = Ahi + S2_A_LO;
    const uint64_t dAh = make_desc(base + HDR);
    const uint64_t dAl = make_desc(base + HDR + S2_A_LO);
    const uint64_t dBh = make_desc(base + HDR + S2_B);
    const uint64_t dBl = make_desc(base + HDR + S2_B + 32768);

    int mph = 0, fph = 0;

    for (int c = 0; c < R / BK; ++c) {            // 3 chunks
        if (c >= 1) { mbar_wait(base + 24, mph); mph ^= 1; }

        if (wid == 0 && elect_one()) {
            const char* srcB = (const char*)g_w2img +
                               (size_t)(((lblk * 4 + (n0 >> 8)) * 3) + c) * S2_B_BYTES;
            MBAR_EXPECT_TX(base + 8, S2_B_BYTES);
            BULK_CP(base + HDR + S2_B, srcB, S2_B_BYTES, base + 8);
        }

        // A tile: 4 uint4 packed loads -> PRMT split -> 2+2 STS.128
        {
            const uint4* s = reinterpret_cast<const uint4*>(a_src + (size_t)c * BK);
            uint4 p0 = s[0], p1 = s[1], p2 = s[2], p3 = s[3];
            uint4 h0, h1, l0, l1;
            h0.x = __byte_perm(p0.x, p0.y, 0x5410); l0.x = __byte_perm(p0.x, p0.y, 0x7632);
            h0.y = __byte_perm(p0.z, p0.w, 0x5410); l0.y = __byte_perm(p0.z, p0.w, 0x7632);
            h0.z = __byte_perm(p1.x, p1.y, 0x5410); l0.z = __byte_perm(p1.x, p1.y, 0x7632);
            h0.w = __byte_perm(p1.z, p1.w, 0x5410); l0.w = __byte_perm(p1.z, p1.w, 0x7632);
            h1.x = __byte_perm(p2.x, p2.y, 0x5410); l1.x = __byte_perm(p2.x, p2.y, 0x7632);
            h1.y = __byte_perm(p2.z, p2.w, 0x5410); l1.y = __byte_perm(p2.z, p2.w, 0x7632);
            h1.z = __byte_perm(p3.x, p3.y, 0x5410); l1.z = __byte_perm(p3.x, p3.y, 0x7632);
            h1.w = __byte_perm(p3.z, p3.w, 0x5410); l1.w = __byte_perm(p3.z, p3.w, 0x7632);
            *reinterpret_cast<uint4*>(Ahi + a_off0) = h0;
            *reinterpret_cast<uint4*>(Ahi + a_off1) = h1;
            *reinterpret_cast<uint4*>(Alo + a_off0) = l0;
            *reinterpret_cast<uint4*>(Alo + a_off1) = l1;
        }
        FENCE_ASYNC();
        __syncthreads();

        if (wid == 0 && elect_one()) {
            mbar_wait(base + 8, fph);   // B arrived
            bool first = (c == 0);
#pragma unroll
            for (int ks = 0; ks < 4; ks++)
                mma_f16_ss(tmem, dAh + ks * 2, dBh + ks * 2, IDESC2, !(first && ks == 0));
#pragma unroll
            for (int ks = 0; ks < 4; ks++)
                mma_f16_ss(tmem, dAh + ks * 2, dBl + ks * 2, IDESC2, true);
#pragma unroll
            for (int ks = 0; ks < 4; ks++)
                mma_f16_ss(tmem, dAl + ks * 2, dBh + ks * 2, IDESC2, true);
            TC_COMMIT(base + 24);
        }
        fph ^= 1;
    }

    mbar_wait(base + 24, mph);
    TC_FENCE_AFTER();
    __syncthreads();

    // Epilogue in 2 passes of 128 cols (staging 128x129 f32 = 66KB <= buffer)
    float* stg = reinterpret_cast<float*>(sm + HDR);
    for (int cc2 = 0; cc2 < 2; ++cc2) {
        if (wid < 4) {
            const int row = wid * 32 + lid;
#pragma unroll
            for (int cc = 0; cc < 4; ++cc) {
                uint32_t r32[32];
                TC_LD_X32(r32, tmem + cc2 * 128 + cc * 32);
                TC_WAIT_LD();
#pragma unroll
                for (int j = 0; j < 32; ++j) stg[row * 129 + cc * 32 + j] = __uint_as_float(r32[j]);
            }
        }
        __syncthreads();

        const int col = t & 127;
        const int rg = t >> 7;                   // 0..3 -> rows rg*32..rg*32+31
        const float bv = bias[lblk * S + n0 + cc2 * 128 + col];
        float* og = out + (size_t)m0 * OUT_F + lblk * S + n0 + cc2 * 128 + col;
#pragma unroll 4
        for (int i = 0; i < 32; ++i) {
            int row = rg * 32 + i;
            og[(size_t)row * OUT_F] = stg[row * 129 + col] + bv;
        }
        __syncthreads();
    }

    if (wid == 0) TC_DEALLOC(tmem, 256);
#else
    // ---- fp32 SIMT fallback: CTA 128 x 256, K=192, 512 threads ----
    extern __shared__ char smem_raw[];
    float* As = reinterpret_cast<float*>(smem_raw);          // [16][132]
    float* Bs = As + 16 * 132;                               // [16][260]

    const int t = threadIdx.x;
    const int ty = t >> 5;
    const int tx = t & 31;
    const int m0 = blockIdx.x * BM;
    const int n0 = blockIdx.y * N2T;
    const int lblk = blockIdx.z;

    const float* Af = reinterpret_cast<const float*>(g_mid) + (size_t)m0 * MIDW + lblk * R;
    const float* Bg = w2 + (size_t)lblk * S * R + (size_t)n0 * R;

    float c[8][8];
#pragma unroll
    for (int i = 0; i < 8; i++)
#pragma unroll
        for (int j = 0; j < 8; j++) c[i][j] = 0.f;

    for (int k0 = 0; k0 < R; k0 += 16) {
        {
            int u = t;
            int m = u >> 2, kq = (u & 3) << 2;
            float4 v = *reinterpret_cast<const float4*>(Af + (size_t)m * MIDW + k0 + kq);
            As[(kq + 0) * 132 + m] = v.x; As[(kq + 1) * 132 + m] = v.y;
            As[(kq + 2) * 132 + m] = v.z; As[(kq + 3) * 132 + m] = v.w;
        }
        for (int u = t; u < 1024; u += NTHREADS) {
            int q = u >> 2, kq = (u & 3) << 2;
            float4 v = *reinterpret_cast<const float4*>(Bg + (size_t)q * R + k0 + kq);
            Bs[(kq + 0) * 260 + q] = v.x; Bs[(kq + 1) * 260 + q] = v.y;
            Bs[(kq + 2) * 260 + q] = v.z; Bs[(kq + 3) * 260 + q] = v.w;
        }
        __syncthreads();

#pragma unroll
        for (int kk = 0; kk < 16; kk++) {
            float a[8], bb[8];
#pragma unroll
            for (int i = 0; i < 8; i++) a[i] = As[kk * 132 + ty * 8 + i];
#pragma unroll
            for (int j = 0; j < 8; j++) bb[j] = Bs[kk * 260 + tx * 8 + j];
#pragma unroll
            for (int i = 0; i < 8; i++)
#pragma unroll
                for (int j = 0; j < 8; j++)
                    c[i][j] = fmaf(a[i], bb[j], c[i][j]);
        }
        __syncthreads();
    }

#pragma unroll
    for (int j = 0; j < 8; j++) {
        int sg = n0 + tx * 8 + j;
        float bv = bias[lblk * S + sg];
#pragma unroll
        for (int i = 0; i < 8; i++) {
            int m = m0 + ty * 8 + i;
            out[(size_t)m * OUT_F + lblk * S + sg] = c[i][j] + bv;
        }
    }
#endif
}

// ---------------------------------------------------------------------------
extern "C" void kernel_launch(void* const* d_in, const int* in_sizes, int n_in,
                              void* d_out, int out_size)
{
    const float* x    = (const float*)d_in[0];
    const float* w1   = (const float*)d_in[1];
    const float* w2   = (const float*)d_in[2];
    const float* bias = (const float*)d_in[3];
    float* out = (float*)d_out;

    // Unconditional (no static guards): identical work on every call.
    cudaFuncSetAttribute(stage1_kernel, cudaFuncAttributeMaxDynamicSharedMemorySize, SMEM1);
    cudaFuncSetAttribute(stage2_kernel, cudaFuncAttributeMaxDynamicSharedMemorySize, SMEM2);

    conv_w1_kernel<<<1536, 256>>>(w1);
    conv_w2_kernel<<<1536, 256>>>(w2);

    dim3 g1(BATCH / BM, NB1, 1);          // (128, 4)
    stage1_kernel<<<g1, NTHREADS, SMEM1>>>(x, w1);

    dim3 g2(BATCH / BM, S / N2T, NB2);    // (128, 4, 4)
    stage2_kernel<<<g2, NTHREADS, SMEM2>>>(w2, bias, out);
}

// round 13
// speedup vs baseline: 6.0159x; 1.0280x over previous
#include <cuda_runtime.h>
#include <cuda_bf16.h>
#include <cstdint>

// Monarch butterfly linear, tcgen05 bf16 split-precision (hi/lo) GEMMs.
// 2 CTAs/SM single-buffered pipeline; A-tile global loads are software-
// pipelined AHEAD of the mma-done wait so DRAM latency hides behind the
// previous chunk's MMA. B tiles stream via cp.async.bulk from pre-swizzled
// weight images. Plain compute_103 passes get fp32 SIMT fallback.

#if defined(__CUDA_ARCH__) && (defined(__CUDA_ARCH_FEAT_SM103_ALL) || defined(__CUDA_ARCH_FEAT_SM100_ALL))
#define HAS_TCGEN05 1
#else
#define HAS_TCGEN05 0
#endif

constexpr int BATCH = 16384;
constexpr int IN_F  = 4096;
constexpr int OUT_F = 4096;
constexpr int NB1 = 4, NB2 = 4, B1C = 48;
constexpr int P = 1024;   // stage1 K
constexpr int Q = 192;    // stage1 N
constexpr int R = 192;    // stage2 K
constexpr int S = 1024;   // stage2 N per l-block
constexpr int MIDW = NB2 * R;  // 768

constexpr int BM = 128;
constexpr int BK = 64;    // 64 bf16 cols = 128B = one SW128 atom row
constexpr int N2T = 256;  // stage2 N tile
constexpr int NTHREADS = 512;

// Scratch: intermediate packed (bf16 hi | bf16 lo) [48 MB] (fallback: fp32 bits)
__device__ uint32_t g_mid[(size_t)BATCH * MIDW];
// Pre-swizzled weight images (bf16 hi plane | lo plane per chunk), 3 MB each.
// w1: [kblk][chunk16][hi 24K | lo 24K]   w2: [lblk][ntile4][chunk3][hi 32K | lo 32K]
__device__ uint4 g_w1img[4 * 16 * 49152 / 16];
__device__ uint4 g_w2img[4 * 4 * 3 * 65536 / 16];

constexpr int HDR = 1024;
// stage1 buffer (single): Ahi 16K | Alo 16K | B(hi+lo) 48K = 80K
constexpr int S1_A_LO = 16384, S1_B = 32768, S1_BUF = 81920;
constexpr int S1_B_BYTES = 49152;
constexpr int SMEM1 = 1024 + HDR + S1_BUF;              // 83968  -> 2 CTAs/SM
// stage2 buffer (single): Ahi 16K | Alo 16K | B(hi+lo) 64K = 96K
constexpr int S2_A_LO = 16384, S2_B = 32768, S2_BUF = 98304;
constexpr int S2_B_BYTES = 65536;
constexpr int SMEM2 = 1024 + HDR + S2_BUF;              // 100352 -> 2 CTAs/SM

__host__ __device__ __forceinline__ uint32_t sw128(uint32_t byte_off) {
    return byte_off ^ ((byte_off >> 3) & 0x70);
}

// ---------------------------------------------------------------------------
// Weight pre-conversion kernels (plain CUDA, both compile variants)
// ---------------------------------------------------------------------------
__global__ __launch_bounds__(256) void conv_w1_kernel(const float* __restrict__ w1)
{
    int id = blockIdx.x * 256 + threadIdx.x;          // [0, 4*192*512)
    if (id >= 4 * 192 * 512) return;
    int k   = id / (192 * 512);
    int rem = id % (192 * 512);
    int row = rem / 512;
    int col = (rem % 512) * 2;
    float2 v = *reinterpret_cast<const float2*>(w1 + ((size_t)k * Q + row) * P + col);
    __nv_bfloat162 h = __floats2bfloat162_rn(v.x, v.y);
    __nv_bfloat162 l = __floats2bfloat162_rn(v.x - __bfloat162float(h.x),
                                             v.y - __bfloat162float(h.y));
    int chunk = col >> 6, cw = col & 63;
    char* img = (char*)g_w1img + (size_t)(k * 16 + chunk) * 49152;
    uint32_t off = sw128((uint32_t)(row * 128 + cw * 2));
    *reinterpret_cast<uint32_t*>(img + off)         = *reinterpret_cast<uint32_t*>(&h);
    *reinterpret_cast<uint32_t*>(img + 24576 + off) = *reinterpret_cast<uint32_t*>(&l);
}

__global__ __launch_bounds__(256) void conv_w2_kernel(const float* __restrict__ w2)
{
    int id = blockIdx.x * 256 + threadIdx.x;          // [0, 4*1024*96)
    if (id >= 4 * 1024 * 96) return;
    int l   = id / (1024 * 96);
    int rem = id % (1024 * 96);
    int s   = rem / 96;
    int col = (rem % 96) * 2;
    float2 v = *reinterpret_cast<const float2*>(w2 + ((size_t)l * S + s) * R + col);
    __nv_bfloat162 h = __floats2bfloat162_rn(v.x, v.y);
    __nv_bfloat162 lo = __floats2bfloat162_rn(v.x - __bfloat162float(h.x),
                                              v.y - __bfloat162float(h.y));
    int chunk = col >> 6, cw = col & 63;
    int ntile = s >> 8, rt = s & 255;
    char* img = (char*)g_w2img + (size_t)(((l * 4 + ntile) * 3) + chunk) * 65536;
    uint32_t off = sw128((uint32_t)(rt * 128 + cw * 2));
    *reinterpret_cast<uint32_t*>(img + off)         = *reinterpret_cast<uint32_t*>(&h);
    *reinterpret_cast<uint32_t*>(img + 32768 + off) = *reinterpret_cast<uint32_t*>(&lo);
}

#if HAS_TCGEN05
// ---------------------------------------------------------------------------
// PTX helpers (arch-specific pass only)
// ---------------------------------------------------------------------------
__device__ __forceinline__ uint32_t smem_u32(const void* p) {
    uint32_t a;
    asm("{ .reg .u64 t; cvta.to.shared.u64 t, %1; cvt.u32.u64 %0, t; }" : "=r"(a) : "l"(p));
    return a;
}
__device__ __forceinline__ bool elect_one() {
    uint32_t pred;
    asm volatile("{ .reg .pred p; elect.sync _|p, 0xFFFFFFFF; selp.b32 %0, 1, 0, p; }" : "=r"(pred));
    return pred != 0;
}
static constexpr uint64_t DESC_BASE_SW128 =
    (uint64_t(2)  << 61) | (uint64_t(1) << 46) | (uint64_t(64) << 32) | (uint64_t(1) << 16);
__device__ __forceinline__ uint64_t make_desc(uint32_t smem_addr) {
    return DESC_BASE_SW128 | ((uint64_t)(smem_addr >> 4) & 0x3FFF);
}

#define TC_ALLOC(smem_ptr_addr, n) \
    asm volatile("tcgen05.alloc.cta_group::1.sync.aligned.shared::cta.b32 [%0], %1;" \
                 :: "r"(smem_ptr_addr), "r"((uint32_t)(n)) : "memory")
#define TC_DEALLOC(tmem, n) \
    asm volatile("tcgen05.dealloc.cta_group::1.sync.aligned.b32 %0, %1;" :: "r"(tmem), "r"((uint32_t)(n)))
#define TC_RELINQ() \
    asm volatile("tcgen05.relinquish_alloc_permit.cta_group::1.sync.aligned;")
#define TC_COMMIT(mbar) \
    asm volatile("tcgen05.commit.cta_group::1.mbarrier::arrive::one.shared::cluster.b64 [%0];" \
                 :: "r"(mbar) : "memory")
#define TC_FENCE_AFTER()  asm volatile("tcgen05.fence::after_thread_sync;" ::: "memory")
#define TC_WAIT_LD()      asm volatile("tcgen05.wait::ld.sync.aligned;" ::: "memory")
#define FENCE_ASYNC()     asm volatile("fence.proxy.async.shared::cta;" ::: "memory")
#define MBAR_INIT(mbar, n) \
    asm volatile("mbarrier.init.shared.b64 [%0], %1;" :: "r"(mbar), "r"((uint32_t)(n)) : "memory")
#define MBAR_EXPECT_TX(mbar, bytes) \
    asm volatile("mbarrier.arrive.expect_tx.shared.b64 _, [%0], %1;" \
                 :: "r"(mbar), "r"((uint32_t)(bytes)) : "memory")
#define BULK_CP(dst_smem, src_gmem, bytes, mbar) \
    asm volatile("cp.async.bulk.shared::cta.global.mbarrier::complete_tx::bytes [%0], [%1], %2, [%3];" \
                 :: "r"(dst_smem), "l"(src_gmem), "r"((uint32_t)(bytes)), "r"(mbar) : "memory")

__device__ __forceinline__ void mbar_wait(uint32_t mbar, int parity) {
    uint32_t done;
    asm volatile("{ .reg .pred p; mbarrier.try_wait.parity.acquire.cta.shared::cta.b64 p, [%1], %2; selp.b32 %0, 1, 0, p; }"
                 : "=r"(done) : "r"(mbar), "r"((uint32_t)parity) : "memory");
    if (!done) {
        asm volatile(
            "{ .reg .pred P1;\n"
            "WAIT_%=: mbarrier.try_wait.parity.acquire.cta.shared::cta.b64 P1, [%0], %1, 0x989680;\n"
            "@P1 bra.uni DONE_%=;\n"
            "bra.uni WAIT_%=;\n"
            "DONE_%=: }"
            :: "r"(mbar), "r"((uint32_t)parity) : "memory");
    }
}

__device__ __forceinline__ void mma_f16_ss(uint32_t d_tmem, uint64_t a_desc, uint64_t b_desc,
                                           uint32_t idesc, bool acc) {
    uint32_t en = acc ? 1u : 0u;
    asm volatile(
        "{ .reg .pred p; setp.ne.u32 p, %4, 0;\n"
        "tcgen05.mma.cta_group::1.kind::f16 [%0], %1, %2, %3, {%5, %5, %5, %5}, p; }"
        :: "r"(d_tmem), "l"(a_desc), "l"(b_desc), "r"(idesc), "r"(en), "r"(0u)
        : "memory");
}

#define TC_LD_X32(r, addr) \
    asm volatile("tcgen05.ld.sync.aligned.32x32b.x32.b32 " \
        "{%0,%1,%2,%3,%4,%5,%6,%7,%8,%9,%10,%11,%12,%13,%14,%15," \
        "%16,%17,%18,%19,%20,%21,%22,%23,%24,%25,%26,%27,%28,%29,%30,%31}, [%32];" \
        : "=r"((r)[0]),"=r"((r)[1]),"=r"((r)[2]),"=r"((r)[3]),"=r"((r)[4]),"=r"((r)[5]),"=r"((r)[6]),"=r"((r)[7]), \
          "=r"((r)[8]),"=r"((r)[9]),"=r"((r)[10]),"=r"((r)[11]),"=r"((r)[12]),"=r"((r)[13]),"=r"((r)[14]),"=r"((r)[15]), \
          "=r"((r)[16]),"=r"((r)[17]),"=r"((r)[18]),"=r"((r)[19]),"=r"((r)[20]),"=r"((r)[21]),"=r"((r)[22]),"=r"((r)[23]), \
          "=r"((r)[24]),"=r"((r)[25]),"=r"((r)[26]),"=r"((r)[27]),"=r"((r)[28]),"=r"((r)[29]),"=r"((r)[30]),"=r"((r)[31]) \
        : "r"(addr))

constexpr uint32_t IDESC1 = (8u << 24) | ((Q   / 8u) << 17) | (1u << 10) | (1u << 7) | (1u << 4); // M=128,N=192
constexpr uint32_t IDESC2 = (8u << 24) | ((N2T / 8u) << 17) | (1u << 10) | (1u << 7) | (1u << 4); // M=128,N=256

__device__ __forceinline__ uint32_t pack_hi(float a, float b) {
    __nv_bfloat162 h = __floats2bfloat162_rn(a, b);
    return *reinterpret_cast<uint32_t*>(&h);
}
__device__ __forceinline__ uint32_t pack_lo(float a, float b, uint32_t hibits) {
    __nv_bfloat162 h = *reinterpret_cast<__nv_bfloat162*>(&hibits);
    __nv_bfloat162 l = __floats2bfloat162_rn(a - __bfloat162float(h.x),
                                             b - __bfloat162float(h.y));
    return *reinterpret_cast<uint32_t*>(&l);
}
#endif  // HAS_TCGEN05

// Barrier slots within HDR (relative to base):
//   +8  full   (bulk-cp B-tile completion, tx-based)
//   +24 mma    (MMA commit)

// ---------------------------------------------------------------------------
// Stage 1: grid (128, 4), 512 threads, dyn smem SMEM1, 2 CTAs/SM
// ---------------------------------------------------------------------------
__global__ __launch_bounds__(NTHREADS, 2) void stage1_kernel(const float* __restrict__ x,
                                                             const float* __restrict__ w1)
{
#if HAS_TCGEN05
    extern __shared__ char smem_raw[];
    const uint32_t raw = smem_u32(smem_raw);
    const uint32_t base = (raw + 1023u) & ~1023u;
    char* sm = smem_raw + (base - raw);

    const int t = threadIdx.x;
    const int wid = t >> 5, lid = t & 31;
    const int m0 = blockIdx.x * BM;
    const int kblk = blockIdx.y;

    if (t == 0) { MBAR_INIT(base + 8, 1); MBAR_INIT(base + 24, 1); }
    __syncthreads();
    // Issue chunk-0 B copy before the (slow) TMEM alloc to overlap prologue.
    if (wid == 1 && elect_one()) {
        const char* srcB = (const char*)g_w1img + (size_t)(kblk * 16 + 0) * S1_B_BYTES;
        MBAR_EXPECT_TX(base + 8, S1_B_BYTES);
        BULK_CP(base + HDR + S1_B, srcB, S1_B_BYTES, base + 8);
    }
    if (wid == 0) { TC_ALLOC(base, 256); TC_RELINQ(); }
    __syncthreads();
    uint32_t tmem;
    asm volatile("ld.shared.b32 %0, [%1];" : "=r"(tmem) : "r"(base));

    const float* Ag = x + (size_t)m0 * IN_F + (size_t)kblk * P;

    // A-fill addressing: thread covers row = t>>2, cols [seg*16, seg*16+16)
    const int arow = t >> 2, aseg = t & 3;
    const uint32_t a_off0 = sw128((uint32_t)(arow * 128 + aseg * 32));
    const uint32_t a_off1 = sw128((uint32_t)(arow * 128 + aseg * 32 + 16));
    const float* a_src = Ag + (size_t)arow * IN_F + aseg * 16;

    char* Ahi = sm + HDR;
    char* Alo = Ahi + S1_A_LO;
    const uint64_t dAh = make_desc(base + HDR);
    const uint64_t dAl = make_desc(base + HDR + S1_A_LO);
    const uint64_t dBh = make_desc(base + HDR + S1_B);
    const uint64_t dBl = make_desc(base + HDR + S1_B + 24576);

    int mph = 0, fph = 0;

    for (int c = 0; c < P / BK; ++c) {            // 16 chunks
        // Prefetch A for this chunk BEFORE waiting on buffer-free: LDGs fly
        // during the mma-wait (and the co-resident CTA's MMA).
        const float4* s = reinterpret_cast<const float4*>(a_src + (size_t)c * BK);
        float4 a0 = s[0], a1 = s[1], a2 = s[2], a3 = s[3];

        if (c >= 1) { mbar_wait(base + 24, mph); mph ^= 1; }

        if (c >= 1 && wid == 0 && elect_one()) {
            const char* srcB = (const char*)g_w1img + (size_t)(kblk * 16 + c) * S1_B_BYTES;
            MBAR_EXPECT_TX(base + 8, S1_B_BYTES);
            BULK_CP(base + HDR + S1_B, srcB, S1_B_BYTES, base + 8);
        }

        // Convert + store prefetched A (buffer now free)
        {
            uint4 h0, h1, l0, l1;
            h0.x = pack_hi(a0.x, a0.y); l0.x = pack_lo(a0.x, a0.y, h0.x);
            h0.y = pack_hi(a0.z, a0.w); l0.y = pack_lo(a0.z, a0.w, h0.y);
            h0.z = pack_hi(a1.x, a1.y); l0.z = pack_lo(a1.x, a1.y, h0.z);
            h0.w = pack_hi(a1.z, a1.w); l0.w = pack_lo(a1.z, a1.w, h0.w);
            h1.x = pack_hi(a2.x, a2.y); l1.x = pack_lo(a2.x, a2.y, h1.x);
            h1.y = pack_hi(a2.z, a2.w); l1.y = pack_lo(a2.z, a2.w, h1.y);
            h1.z = pack_hi(a3.x, a3.y); l1.z = pack_lo(a3.x, a3.y, h1.z);
            h1.w = pack_hi(a3.z, a3.w); l1.w = pack_lo(a3.z, a3.w, h1.w);
            *reinterpret_cast<uint4*>(Ahi + a_off0) = h0;
            *reinterpret_cast<uint4*>(Ahi + a_off1) = h1;
            *reinterpret_cast<uint4*>(Alo + a_off0) = l0;
            *reinterpret_cast<uint4*>(Alo + a_off1) = l1;
        }
        FENCE_ASYNC();
        __syncthreads();

        if (wid == 0 && elect_one()) {
            mbar_wait(base + 8, fph);   // B arrived
            bool first = (c == 0);
#pragma unroll
            for (int ks = 0; ks < 4; ks++)
                mma_f16_ss(tmem, dAh + ks * 2, dBh + ks * 2, IDESC1, !(first && ks == 0));
#pragma unroll
            for (int ks = 0; ks < 4; ks++)
                mma_f16_ss(tmem, dAh + ks * 2, dBl + ks * 2, IDESC1, true);
#pragma unroll
            for (int ks = 0; ks < 4; ks++)
                mma_f16_ss(tmem, dAl + ks * 2, dBh + ks * 2, IDESC1, true);
            TC_COMMIT(base + 24);
        }
        fph ^= 1;
    }

    mbar_wait(base + 24, mph);
    TC_FENCE_AFTER();
    __syncthreads();

    // Epilogue in 3 passes of 64 cols (staging 128x65 f32 = 33.3KB <= buffer)
    float* stg = reinterpret_cast<float*>(sm + HDR);
    for (int cc3 = 0; cc3 < 3; ++cc3) {
        if (wid < 4) {
            const int row = wid * 32 + lid;
            uint32_t r32[32];
            TC_LD_X32(r32, tmem + cc3 * 64);
            TC_WAIT_LD();
#pragma unroll
            for (int j = 0; j < 32; ++j) stg[row * 65 + j] = __uint_as_float(r32[j]);
            TC_LD_X32(r32, tmem + cc3 * 64 + 32);
            TC_WAIT_LD();
#pragma unroll
            for (int j = 0; j < 32; ++j) stg[row * 65 + 32 + j] = __uint_as_float(r32[j]);
        }
        __syncthreads();

        for (int u = t; u < 128 * 64; u += NTHREADS) {
            int r = u >> 6, q = (u & 63) + cc3 * 64;
            int l = q / B1C, b1 = q - l * B1C;
            float f = stg[r * 65 + (u & 63)];
            __nv_bfloat16 h = __float2bfloat16_rn(f);
            __nv_bfloat16 lo = __float2bfloat16_rn(f - __bfloat162float(h));
            uint32_t packed = (uint32_t)__bfloat16_as_ushort(h) |
                              ((uint32_t)__bfloat16_as_ushort(lo) << 16);
            g_mid[(size_t)(m0 + r) * MIDW + l * R + kblk * B1C + b1] = packed;
        }
        __syncthreads();
    }

    if (wid == 0) TC_DEALLOC(tmem, 256);
#else
    // ---- fp32 SIMT fallback: CTA 128 x 192, K=1024, 512 threads ----
    extern __shared__ char smem_raw[];
    float* As = reinterpret_cast<float*>(smem_raw);          // [16][132]
    float* Bs = As + 16 * 132;                               // [16][196]

    const int t = threadIdx.x;
    const int ty = t >> 5;
    const int tx = t & 31;
    const int m0 = blockIdx.x * BM;
    const int kblk = blockIdx.y;

    const float* Ag = x  + (size_t)m0 * IN_F + (size_t)kblk * P;
    const float* Bg = w1 + (size_t)kblk * Q * P;

    float c[8][6];
#pragma unroll
    for (int i = 0; i < 8; i++)
#pragma unroll
        for (int j = 0; j < 6; j++) c[i][j] = 0.f;

    for (int k0 = 0; k0 < P; k0 += 16) {
        {
            int u = t;
            int m = u >> 2, kq = (u & 3) << 2;
            float4 v = *reinterpret_cast<const float4*>(Ag + (size_t)m * IN_F + k0 + kq);
            As[(kq + 0) * 132 + m] = v.x; As[(kq + 1) * 132 + m] = v.y;
            As[(kq + 2) * 132 + m] = v.z; As[(kq + 3) * 132 + m] = v.w;
        }
        for (int u = t; u < 768; u += NTHREADS) {
            int q = u >> 2, kq = (u & 3) << 2;
            float4 v = *reinterpret_cast<const float4*>(Bg + (size_t)q * P + k0 + kq);
            Bs[(kq + 0) * 196 + q] = v.x; Bs[(kq + 1) * 196 + q] = v.y;
            Bs[(kq + 2) * 196 + q] = v.z; Bs[(kq + 3) * 196 + q] = v.w;
        }
        __syncthreads();

#pragma unroll
        for (int kk = 0; kk < 16; kk++) {
            float a[8], bb[6];
#pragma unroll
            for (int i = 0; i < 8; i++) a[i] = As[kk * 132 + ty * 8 + i];
#pragma unroll
            for (int j = 0; j < 6; j++) bb[j] = Bs[kk * 196 + tx * 6 + j];
#pragma unroll
            for (int i = 0; i < 8; i++)
#pragma unroll
                for (int j = 0; j < 6; j++)
                    c[i][j] = fmaf(a[i], bb[j], c[i][j]);
        }
        __syncthreads();
    }

#pragma unroll
    for (int i = 0; i < 8; i++) {
        int m = m0 + ty * 8 + i;
#pragma unroll
        for (int j = 0; j < 6; j++) {
            int q = tx * 6 + j;
            int l = q / B1C, b1 = q - l * B1C;
            g_mid[(size_t)m * MIDW + l * R + kblk * B1C + b1] = __float_as_uint(c[i][j]);
        }
    }
#endif
}

// ---------------------------------------------------------------------------
// Stage 2: grid (128, 4, 4), 512 threads, dyn smem SMEM2, 2 CTAs/SM
// ---------------------------------------------------------------------------
__global__ __launch_bounds__(NTHREADS, 2) void stage2_kernel(const float* __restrict__ w2,
                                                             const float* __restrict__ bias,
                                                             float* __restrict__ out)
{
#if HAS_TCGEN05
    extern __shared__ char smem_raw[];
    const uint32_t raw = smem_u32(smem_raw);
    const uint32_t base = (raw + 1023u) & ~1023u;
    char* sm = smem_raw + (base - raw);

    const int t = threadIdx.x;
    const int wid = t >> 5, lid = t & 31;
    const int m0 = blockIdx.x * BM;
    const int n0 = blockIdx.y * N2T;
    const int lblk = blockIdx.z;

    if (t == 0) { MBAR_INIT(base + 8, 1); MBAR_INIT(base + 24, 1); }
    __syncthreads();
    if (wid == 1 && elect_one()) {
        const char* srcB = (const char*)g_w2img +
                           (size_t)(((lblk * 4 + (n0 >> 8)) * 3) + 0) * S2_B_BYTES;
        MBAR_EXPECT_TX(base + 8, S2_B_BYTES);
        BULK_CP(base + HDR + S2_B, srcB, S2_B_BYTES, base + 8);
    }
    if (wid == 0) { TC_ALLOC(base, 256); TC_RELINQ(); }
    __syncthreads();
    uint32_t tmem;
    asm volatile("ld.shared.b32 %0, [%1];" : "=r"(tmem) : "r"(base));

    const uint32_t* Ag = g_mid + (size_t)m0 * MIDW + lblk * R;

    const int arow = t >> 2, aseg = t & 3;       // cols [aseg*16, +16)
    const uint32_t a_off0 = sw128((uint32_t)(arow * 128 + aseg * 32));
    const uint32_t a_off1 = sw128((uint32_t)(arow * 128 + aseg * 32 + 16));
    const uint32_t* a_src = Ag + (size_t)arow * MIDW + aseg * 16;

    char* Ahi = sm + HDR;
    char* Alo = Ahi + S2_A_LO;
    const uint64_t dAh = make_desc(base + HDR);
    const uint64_t dAl = make_desc(base + HDR + S2_A_LO);
    const uint64_t dBh = make_desc(base + HDR + S2_B);
    const uint64_t dBl = make_desc(base + HDR + S2_B + 32768);

    int mph = 0, fph = 0;

    for (int c = 0; c < R / BK; ++c) {            // 3 chunks
        // Prefetch packed A ahead of the buffer-free wait.
        const uint4* s = reinterpret_cast<const uint4*>(a_src + (size_t)c * BK);
        uint4 p0 = s[0], p1 = s[1], p2 = s[2], p3 = s[3];

        if (c >= 1) { mbar_wait(base + 24, mph); mph ^= 1; }

        if (c >= 1 && wid == 0 && elect_one()) {
            const char* srcB = (const char*)g_w2img +
                               (size_t)(((lblk * 4 + (n0 >> 8)) * 3) + c) * S2_B_BYTES;
            MBAR_EXPECT_TX(base + 8, S2_B_BYTES);
            BULK_CP(base + HDR + S2_B, srcB, S2_B_BYTES, base + 8);
        }

        // PRMT split + store (buffer free now)
        {
            uint4 h0, h1, l0, l1;
            h0.x = __byte_perm(p0.x, p0.y, 0x5410); l0.x = __byte_perm(p0.x, p0.y, 0x7632);
            h0.y = __byte_perm(p0.z, p0.w, 0x5410); l0.y = __byte_perm(p0.z, p0.w, 0x7632);
            h0.z = __byte_perm(p1.x, p1.y, 0x5410); l0.z = __byte_perm(p1.x, p1.y, 0x7632);
            h0.w = __byte_perm(p1.z, p1.w, 0x5410); l0.w = __byte_perm(p1.z, p1.w, 0x7632);
            h1.x = __byte_perm(p2.x, p2.y, 0x5410); l1.x = __byte_perm(p2.x, p2.y, 0x7632);
            h1.y = __byte_perm(p2.z, p2.w, 0x5410); l1.y = __byte_perm(p2.z, p2.w, 0x7632);
            h1.z = __byte_perm(p3.x, p3.y, 0x5410); l1.z = __byte_perm(p3.x, p3.y, 0x7632);
            h1.w = __byte_perm(p3.z, p3.w, 0x5410); l1.w = __byte_perm(p3.z, p3.w, 0x7632);
            *reinterpret_cast<uint4*>(Ahi + a_off0) = h0;
            *reinterpret_cast<uint4*>(Ahi + a_off1) = h1;
            *reinterpret_cast<uint4*>(Alo + a_off0) = l0;
            *reinterpret_cast<uint4*>(Alo + a_off1) = l1;
        }
        FENCE_ASYNC();
        __syncthreads();

        if (wid == 0 && elect_one()) {
            mbar_wait(base + 8, fph);   // B arrived
            bool first = (c == 0);
#pragma unroll
            for (int ks = 0; ks < 4; ks++)
                mma_f16_ss(tmem, dAh + ks * 2, dBh + ks * 2, IDESC2, !(first && ks == 0));
#pragma unroll
            for (int ks = 0; ks < 4; ks++)
                mma_f16_ss(tmem, dAh + ks * 2, dBl + ks * 2, IDESC2, true);
#pragma unroll
            for (int ks = 0; ks < 4; ks++)
                mma_f16_ss(tmem, dAl + ks * 2, dBh + ks * 2, IDESC2, true);
            TC_COMMIT(base + 24);
        }
        fph ^= 1;
    }

    mbar_wait(base + 24, mph);
    TC_FENCE_AFTER();
    __syncthreads();

    // Epilogue in 2 passes of 128 cols (staging 128x129 f32 = 66KB <= buffer)
    float* stg = reinterpret_cast<float*>(sm + HDR);
    for (int cc2 = 0; cc2 < 2; ++cc2) {
        if (wid < 4) {
            const int row = wid * 32 + lid;
#pragma unroll
            for (int cc = 0; cc < 4; ++cc) {
                uint32_t r32[32];
                TC_LD_X32(r32, tmem + cc2 * 128 + cc * 32);
                TC_WAIT_LD();
#pragma unroll
                for (int j = 0; j < 32; ++j) stg[row * 129 + cc * 32 + j] = __uint_as_float(r32[j]);
            }
        }
        __syncthreads();

        const int col = t & 127;
        const int rg = t >> 7;                   // 0..3 -> rows rg*32..rg*32+31
        const float bv = bias[lblk * S + n0 + cc2 * 128 + col];
        float* og = out + (size_t)m0 * OUT_F + lblk * S + n0 + cc2 * 128 + col;
#pragma unroll 4
        for (int i = 0; i < 32; ++i) {
            int row = rg * 32 + i;
            og[(size_t)row * OUT_F] = stg[row * 129 + col] + bv;
        }
        __syncthreads();
    }

    if (wid == 0) TC_DEALLOC(tmem, 256);
#else
    // ---- fp32 SIMT fallback: CTA 128 x 256, K=192, 512 threads ----
    extern __shared__ char smem_raw[];
    float* As = reinterpret_cast<float*>(smem_raw);          // [16][132]
    float* Bs = As + 16 * 132;                               // [16][260]

    const int t = threadIdx.x;
    const int ty = t >> 5;
    const int tx = t & 31;
    const int m0 = blockIdx.x * BM;
    const int n0 = blockIdx.y * N2T;
    const int lblk = blockIdx.z;

    const float* Af = reinterpret_cast<const float*>(g_mid) + (size_t)m0 * MIDW + lblk * R;
    const float* Bg = w2 + (size_t)lblk * S * R + (size_t)n0 * R;

    float c[8][8];
#pragma unroll
    for (int i = 0; i < 8; i++)
#pragma unroll
        for (int j = 0; j < 8; j++) c[i][j] = 0.f;

    for (int k0 = 0; k0 < R; k0 += 16) {
        {
            int u = t;
            int m = u >> 2, kq = (u & 3) << 2;
            float4 v = *reinterpret_cast<const float4*>(Af + (size_t)m * MIDW + k0 + kq);
            As[(kq + 0) * 132 + m] = v.x; As[(kq + 1) * 132 + m] = v.y;
            As[(kq + 2) * 132 + m] = v.z; As[(kq + 3) * 132 + m] = v.w;
        }
        for (int u = t; u < 1024; u += NTHREADS) {
            int q = u >> 2, kq = (u & 3) << 2;
            float4 v = *reinterpret_cast<const float4*>(Bg + (size_t)q * R + k0 + kq);
            Bs[(kq + 0) * 260 + q] = v.x; Bs[(kq + 1) * 260 + q] = v.y;
            Bs[(kq + 2) * 260 + q] = v.z; Bs[(kq + 3) * 260 + q] = v.w;
        }
        __syncthreads();

#pragma unroll
        for (int kk = 0; kk < 16; kk++) {
            float a[8], bb[8];
#pragma unroll
            for (int i = 0; i < 8; i++) a[i] = As[kk * 132 + ty * 8 + i];
#pragma unroll
            for (int j = 0; j < 8; j++) bb[j] = Bs[kk * 260 + tx * 8 + j];
#pragma unroll
            for (int i = 0; i < 8; i++)
#pragma unroll
                for (int j = 0; j < 8; j++)
                    c[i][j] = fmaf(a[i], bb[j], c[i][j]);
        }
        __syncthreads();
    }

#pragma unroll
    for (int j = 0; j < 8; j++) {
        int sg = n0 + tx * 8 + j;
        float bv = bias[lblk * S + sg];
#pragma unroll
        for (int i = 0; i < 8; i++) {
            int m = m0 + ty * 8 + i;
            out[(size_t)m * OUT_F + lblk * S + sg] = c[i][j] + bv;
        }
    }
#endif
}

// ---------------------------------------------------------------------------
extern "C" void kernel_launch(void* const* d_in, const int* in_sizes, int n_in,
                              void* d_out, int out_size)
{
    const float* x    = (const float*)d_in[0];
    const float* w1   = (const float*)d_in[1];
    const float* w2   = (const float*)d_in[2];
    const float* bias = (const float*)d_in[3];
    float* out = (float*)d_out;

    // Unconditional (no static guards): identical work on every call.
    cudaFuncSetAttribute(stage1_kernel, cudaFuncAttributeMaxDynamicSharedMemorySize, SMEM1);
    cudaFuncSetAttribute(stage2_kernel, cudaFuncAttributeMaxDynamicSharedMemorySize, SMEM2);

    conv_w1_kernel<<<1536, 256>>>(w1);
    conv_w2_kernel<<<1536, 256>>>(w2);

    dim3 g1(BATCH / BM, NB1, 1);          // (128, 4)
    stage1_kernel<<<g1, NTHREADS, SMEM1>>>(x, w1);

    dim3 g2(BATCH / BM, S / N2T, NB2);    // (128, 4, 4)
    stage2_kernel<<<g2, NTHREADS, SMEM2>>>(w2, bias, out);
}